// round 1
// baseline (speedup 1.0000x reference)
#include <cuda_runtime.h>
#include <math.h>

#define NN   1024
#define IND  256
#define ED   32
#define HID  32
#define ODIM 128
#define NE   100000

// ---- scratch (device globals; no allocation allowed) ----
__device__ float g_proj[NE * ED];      // tanh(edge_emb @ We + be)
__device__ float g_xatt[NN * HID];
__device__ float g_natt[NN * HID];
__device__ float g_value[NN * ODIM];   // neigh @ Wv + bv
__device__ float g_ws[NN * NN];        // softmax weights
__device__ float g_we[NN * ED];        // ws-weighted edge embeddings

// ============================================================
// proj[e,h] = tanh( edge_emb[e,:] @ We + be )  -- one warp per row
// ============================================================
__global__ void __launch_bounds__(256) proj_kernel(const float* __restrict__ emb,
                                                   const float* __restrict__ We,
                                                   const float* __restrict__ be) {
    __shared__ float sW[32 * 32];
    __shared__ float sb[32];
    int tid = threadIdx.x;
    for (int i = tid; i < 1024; i += blockDim.x) sW[i] = We[i];
    if (tid < 32) sb[tid] = be[tid];
    __syncthreads();
    int lane = tid & 31, warp = tid >> 5;
    int nw = (blockDim.x >> 5) * gridDim.x;
    for (int e = blockIdx.x * (blockDim.x >> 5) + warp; e < NE; e += nw) {
        float v = emb[e * 32 + lane];
        float acc = sb[lane];
#pragma unroll
        for (int d = 0; d < 32; d++)
            acc = fmaf(__shfl_sync(0xffffffffu, v, d), sW[d * 32 + lane], acc);
        g_proj[e * 32 + lane] = tanhf(acc);
    }
}

// ============================================================
// attention MLP: out = tanh(X@W1 + b1)@W2 + b2   (rows of 256 -> 32)
// one warp per row; which=0 -> g_xatt, which=1 -> g_natt
// ============================================================
__global__ void __launch_bounds__(256) att_kernel(const float* __restrict__ X,
                                                  const float* __restrict__ W1,
                                                  const float* __restrict__ b1,
                                                  const float* __restrict__ W2,
                                                  const float* __restrict__ b2,
                                                  int which) {
    __shared__ float sx[8][IND];
    int warp = threadIdx.x >> 5, lane = threadIdx.x & 31;
    int row = blockIdx.x * 8 + warp;
    for (int d = lane; d < IND; d += 32) sx[warp][d] = X[row * IND + d];
    __syncwarp();
    float acc = b1[lane];
#pragma unroll 8
    for (int d = 0; d < IND; d++)
        acc = fmaf(sx[warp][d], W1[d * 32 + lane], acc);
    float h = tanhf(acc);
    float a2 = b2[lane];
#pragma unroll
    for (int j = 0; j < 32; j++)
        a2 = fmaf(__shfl_sync(0xffffffffu, h, j), W2[j * 32 + lane], a2);
    float* dst = which ? g_natt : g_xatt;
    dst[row * 32 + lane] = a2;
}

// ============================================================
// out[r,c] = X[r,:] @ W + b   for 256->128; 16 rows per block
// which=0 -> g_value (stride 128); which=1 -> outp (stride 256, cols 0:128)
// ============================================================
__global__ void __launch_bounds__(256) mlp_kernel(const float* __restrict__ X,
                                                  const float* __restrict__ W,
                                                  const float* __restrict__ b,
                                                  float* __restrict__ outp,
                                                  int which) {
    __shared__ float sx[16][IND];
    int r0 = blockIdx.x * 16;
    for (int i = threadIdx.x; i < 16 * IND; i += 256) {
        int r = i >> 8, c = i & 255;
        sx[r][c] = X[(r0 + r) * IND + c];
    }
    __syncthreads();
    int c = threadIdx.x & 127;
    int rh = threadIdx.x >> 7;   // 0..1
    float acc[8];
    float bb = b[c];
#pragma unroll
    for (int i = 0; i < 8; i++) acc[i] = bb;
    for (int d = 0; d < IND; d++) {
        float w = W[d * 128 + c];
#pragma unroll
        for (int i = 0; i < 8; i++)
            acc[i] = fmaf(sx[rh * 8 + i][d], w, acc[i]);
    }
    if (which == 0) {
#pragma unroll
        for (int i = 0; i < 8; i++) g_value[(r0 + rh * 8 + i) * ODIM + c] = acc[i];
    } else {
#pragma unroll
        for (int i = 0; i < 8; i++) outp[(r0 + rh * 8 + i) * (2 * ODIM) + c] = acc[i];
    }
}

// ============================================================
// per-row: scores (node term + gathered edge term) -> leaky -> mask ->
// softmax -> write ws -> weighted edge-embedding sum
// one block (256 thr) per row n; groups of 8 lanes per k
// ============================================================
__global__ void __launch_bounds__(256) row_kernel(const int* __restrict__ adj,
                                                  const float* __restrict__ emb) {
    __shared__ int sadj[NN];
    __shared__ float ss[NN];
    __shared__ __align__(16) float sx[32];
    __shared__ float red[8];
    __shared__ __align__(16) float swe[32 * 32];

    int n = blockIdx.x;
    int tid = threadIdx.x;
    for (int k = tid; k < NN; k += 256) sadj[k] = adj[n * NN + k];
    if (tid < 32) sx[tid] = g_xatt[n * 32 + tid];
    __syncthreads();

    int g = tid >> 3, l8 = tid & 7;
    float4 x4 = reinterpret_cast<const float4*>(sx)[l8];
    const float4* proj4 = reinterpret_cast<const float4*>(g_proj);
    const float4* natt4 = reinterpret_cast<const float4*>(g_natt);
    const float4* emb4  = reinterpret_cast<const float4*>(emb);

    // ---- phase 1: scores ----
#pragma unroll 4
    for (int it = 0; it < 32; ++it) {
        int k = it * 32 + g;
        int e = sadj[k];
        float4 p  = proj4[e * 8 + l8];   // random 128B row gather (L2)
        float4 na = natt4[k * 8 + l8];   // streamed
        float part = fmaf(p.x + na.x, x4.x,
                     fmaf(p.y + na.y, x4.y,
                     fmaf(p.z + na.z, x4.z, (p.w + na.w) * x4.w)));
        part += __shfl_xor_sync(0xffffffffu, part, 1);
        part += __shfl_xor_sync(0xffffffffu, part, 2);
        part += __shfl_xor_sync(0xffffffffu, part, 4);
        if (l8 == 0) {
            float s = part > 0.f ? part : 0.01f * part;  // leaky_relu(0.01)
            ss[k] = (e > 0) ? s : -9e15f;                // mask adj>0
        }
    }
    __syncthreads();

    // ---- phase 2: softmax over k ----
    float m = -3.4e38f;
    for (int k = tid; k < NN; k += 256) m = fmaxf(m, ss[k]);
#pragma unroll
    for (int o = 16; o; o >>= 1) m = fmaxf(m, __shfl_xor_sync(0xffffffffu, m, o));
    if ((tid & 31) == 0) red[tid >> 5] = m;
    __syncthreads();
    if (tid == 0) {
        float t = red[0];
        for (int i = 1; i < 8; i++) t = fmaxf(t, red[i]);
        red[0] = t;
    }
    __syncthreads();
    float M = red[0];
    __syncthreads();

    float Z = 0.f;
    for (int k = tid; k < NN; k += 256) {
        float ev = __expf(ss[k] - M);
        ss[k] = ev;
        Z += ev;
    }
#pragma unroll
    for (int o = 16; o; o >>= 1) Z += __shfl_xor_sync(0xffffffffu, Z, o);
    if ((tid & 31) == 0) red[tid >> 5] = Z;
    __syncthreads();
    if (tid == 0) {
        float t = 0.f;
        for (int i = 0; i < 8; i++) t += red[i];
        red[0] = t;
    }
    __syncthreads();
    float inv = 1.f / red[0];
    for (int k = tid; k < NN; k += 256) {
        float w = ss[k] * inv;
        ss[k] = w;
        g_ws[n * NN + k] = w;
    }
    __syncthreads();

    // ---- phase 3: we[n,:] = sum_k ws[k] * edge_emb[adj[n,k],:] ----
    float4 acc = make_float4(0.f, 0.f, 0.f, 0.f);
#pragma unroll 4
    for (int it = 0; it < 32; ++it) {
        int k = it * 32 + g;
        float w = ss[k];
        int e = sadj[k];
        float4 em = emb4[e * 8 + l8];    // second random gather (L2)
        acc.x += w * em.x; acc.y += w * em.y;
        acc.z += w * em.z; acc.w += w * em.w;
    }
    reinterpret_cast<float4*>(swe)[g * 8 + l8] = acc;
    __syncthreads();
    if (tid < 32) {
        float a = 0.f;
        for (int gg = 0; gg < 32; gg++) a += swe[gg * 32 + tid];
        g_we[n * 32 + tid] = a;
    }
}

// ============================================================
// out[n,128:256] = ws @ value + we @ Wfe + bfe
// tiled SGEMM: 32x32 tiles, 256 threads, 2x2 per thread; grid (32,4)
// ============================================================
__global__ void __launch_bounds__(256) agg_kernel(const float* __restrict__ Wfe,
                                                  const float* __restrict__ bfe,
                                                  float* __restrict__ outp) {
    __shared__ float sA[32][33];
    __shared__ float sB[32][33];
    int bm = blockIdx.x * 32, bn = blockIdx.y * 32;
    int tx = threadIdx.x & 15, ty = threadIdx.x >> 4;
    float a00 = 0, a01 = 0, a10 = 0, a11 = 0;
    for (int kt = 0; kt < NN; kt += 32) {
        for (int i = threadIdx.x; i < 1024; i += 256) {
            int r = i >> 5, c2 = i & 31;
            sA[r][c2] = g_ws[(bm + r) * NN + kt + c2];
            sB[r][c2] = g_value[(kt + r) * ODIM + bn + c2];
        }
        __syncthreads();
#pragma unroll
        for (int kk = 0; kk < 32; kk++) {
            float a0 = sA[ty * 2][kk], a1 = sA[ty * 2 + 1][kk];
            float b0 = sB[kk][tx * 2], b1 = sB[kk][tx * 2 + 1];
            a00 = fmaf(a0, b0, a00); a01 = fmaf(a0, b1, a01);
            a10 = fmaf(a1, b0, a10); a11 = fmaf(a1, b1, a11);
        }
        __syncthreads();
    }
    // epilogue: + we @ Wfe
    for (int i = threadIdx.x; i < 1024; i += 256) {
        int r = i >> 5, c2 = i & 31;
        sA[r][c2] = g_we[(bm + r) * 32 + c2];
        sB[r][c2] = Wfe[r * 128 + bn + c2];
    }
    __syncthreads();
#pragma unroll
    for (int kk = 0; kk < 32; kk++) {
        float a0 = sA[ty * 2][kk], a1 = sA[ty * 2 + 1][kk];
        float b0 = sB[kk][tx * 2], b1 = sB[kk][tx * 2 + 1];
        a00 = fmaf(a0, b0, a00); a01 = fmaf(a0, b1, a01);
        a10 = fmaf(a1, b0, a10); a11 = fmaf(a1, b1, a11);
    }
    float bf0 = bfe[bn + tx * 2], bf1 = bfe[bn + tx * 2 + 1];
    int m0 = bm + ty * 2;
    outp[m0 * 256 + 128 + bn + tx * 2]           = a00 + bf0;
    outp[m0 * 256 + 128 + bn + tx * 2 + 1]       = a01 + bf1;
    outp[(m0 + 1) * 256 + 128 + bn + tx * 2]     = a10 + bf0;
    outp[(m0 + 1) * 256 + 128 + bn + tx * 2 + 1] = a11 + bf1;
}

extern "C" void kernel_launch(void* const* d_in, const int* in_sizes, int n_in,
                              void* d_out, int out_size) {
    const float* x     = (const float*)d_in[0];
    const float* neigh = (const float*)d_in[1];
    const float* emb   = (const float*)d_in[2];
    const int*   adj   = (const int*)d_in[3];
    const float* Wx1 = (const float*)d_in[4];  const float* bx1 = (const float*)d_in[5];
    const float* Wx2 = (const float*)d_in[6];  const float* bx2 = (const float*)d_in[7];
    const float* Wn1 = (const float*)d_in[8];  const float* bn1 = (const float*)d_in[9];
    const float* Wn2 = (const float*)d_in[10]; const float* bn2 = (const float*)d_in[11];
    const float* We  = (const float*)d_in[12]; const float* be  = (const float*)d_in[13];
    const float* Wv  = (const float*)d_in[14]; const float* bv  = (const float*)d_in[15];
    const float* Wfe = (const float*)d_in[16]; const float* bfe = (const float*)d_in[17];
    const float* Wfx = (const float*)d_in[18]; const float* bfx = (const float*)d_in[19];
    float* out = (float*)d_out;

    proj_kernel<<<1184, 256>>>(emb, We, be);
    att_kernel<<<128, 256>>>(x,     Wx1, bx1, Wx2, bx2, 0);
    att_kernel<<<128, 256>>>(neigh, Wn1, bn1, Wn2, bn2, 1);
    mlp_kernel<<<64, 256>>>(neigh, Wv,  bv,  nullptr, 0);   // value
    mlp_kernel<<<64, 256>>>(x,     Wfx, bfx, out,     1);   // out[:, :128]
    row_kernel<<<NN, 256>>>(adj, emb);
    agg_kernel<<<dim3(32, 4), 256>>>(Wfe, bfe, out);
}

// round 3
// speedup vs baseline: 1.8475x; 1.8475x over previous
#include <cuda_runtime.h>
#include <math.h>

#define NN   1024
#define IND  256
#define ED   32
#define HID  32
#define ODIM 128
#define NE   100000

// ---- scratch (device globals; no allocation allowed) ----
__device__ float g_proj[NE * ED];        // tanh(edge_emb @ We + be)
__device__ float g_xatt[NN * HID];
__device__ float g_natt[NN * HID];
__device__ float g_value[NN * ODIM];     // neigh @ Wv + bv
__device__ float g_s1[NN * NN];          // x_att @ n_att^T
__device__ float g_ws[NN * NN];          // softmax weights
__device__ float g_we[NN * ED];          // ws-weighted edge embeddings
__device__ float g_part[4 * NN * ODIM];  // ksplit partials of ws@value

// ============================================================
// proj[e,h] = tanh( edge_emb[e,:] @ We + be )
// 32 rows per block, 4 rows per thread; smem-tiled
// ============================================================
__global__ void __launch_bounds__(256) proj_kernel(const float* __restrict__ emb,
                                                   const float* __restrict__ We,
                                                   const float* __restrict__ be) {
    __shared__ float sW[32 * 32];
    __shared__ float sb[32];
    __shared__ __align__(16) float sx[32 * 32];
    int tid = threadIdx.x;
    for (int i = tid; i < 1024; i += 256) sW[i] = We[i];
    if (tid < 32) sb[tid] = be[tid];
    int rows0 = blockIdx.x * 32;
    // stage 32 rows of emb (coalesced float4)
    reinterpret_cast<float4*>(sx)[tid] =
        reinterpret_cast<const float4*>(emb)[rows0 * 8 + tid];
    __syncthreads();
    int col = tid & 31;
    int r0 = (tid >> 5) * 4;
    float acc0 = sb[col], acc1 = acc0, acc2 = acc0, acc3 = acc0;
#pragma unroll
    for (int d = 0; d < 32; d++) {
        float w = sW[d * 32 + col];
        acc0 = fmaf(sx[(r0 + 0) * 32 + d], w, acc0);
        acc1 = fmaf(sx[(r0 + 1) * 32 + d], w, acc1);
        acc2 = fmaf(sx[(r0 + 2) * 32 + d], w, acc2);
        acc3 = fmaf(sx[(r0 + 3) * 32 + d], w, acc3);
    }
    g_proj[(rows0 + r0 + 0) * 32 + col] = tanhf(acc0);
    g_proj[(rows0 + r0 + 1) * 32 + col] = tanhf(acc1);
    g_proj[(rows0 + r0 + 2) * 32 + col] = tanhf(acc2);
    g_proj[(rows0 + r0 + 3) * 32 + col] = tanhf(acc3);
}

// ============================================================
// attention MLP: out = tanh(X@W1 + b1)@W2 + b2   (rows of 256 -> 32)
// ============================================================
__global__ void __launch_bounds__(256) att_kernel(const float* __restrict__ X,
                                                  const float* __restrict__ W1,
                                                  const float* __restrict__ b1,
                                                  const float* __restrict__ W2,
                                                  const float* __restrict__ b2,
                                                  int which) {
    __shared__ float sx[8][IND];
    int warp = threadIdx.x >> 5, lane = threadIdx.x & 31;
    int row = blockIdx.x * 8 + warp;
    for (int d = lane; d < IND; d += 32) sx[warp][d] = X[row * IND + d];
    __syncwarp();
    float acc = b1[lane];
#pragma unroll 8
    for (int d = 0; d < IND; d++)
        acc = fmaf(sx[warp][d], W1[d * 32 + lane], acc);
    float h = tanhf(acc);
    float a2 = b2[lane];
#pragma unroll
    for (int j = 0; j < 32; j++)
        a2 = fmaf(__shfl_sync(0xffffffffu, h, j), W2[j * 32 + lane], a2);
    float* dst = which ? g_natt : g_xatt;
    dst[row * 32 + lane] = a2;
}

// ============================================================
// fused pair of 256->128 GEMMs: z=0: neigh@Wv+bv -> g_value
//                              z=1: x@Wfx+bfx   -> out[:, 0:128]
// 16 rows per block, W staged through smem, 8 outputs/thread
// ============================================================
__global__ void __launch_bounds__(256) gemm2_kernel(const float* __restrict__ neigh,
                                                    const float* __restrict__ Wv,
                                                    const float* __restrict__ bv,
                                                    const float* __restrict__ x,
                                                    const float* __restrict__ Wfx,
                                                    const float* __restrict__ bfx,
                                                    float* __restrict__ outp) {
    __shared__ __align__(16) float sX[16 * IND];   // 16 KB
    __shared__ __align__(16) float sW[32 * 128];   // 16 KB
    int z = blockIdx.y;
    const float* X = z ? x : neigh;
    const float* W = z ? Wfx : Wv;
    const float* b = z ? bfx : bv;
    int tid = threadIdx.x;
    int r0 = blockIdx.x * 16;
    // stage X rows (1024 float4)
#pragma unroll
    for (int j = 0; j < 4; j++) {
        int f = tid + j * 256;
        int r = f >> 6, c4 = f & 63;
        reinterpret_cast<float4*>(sX)[f] =
            reinterpret_cast<const float4*>(X)[(r0 + r) * 64 + c4];
    }
    int c = tid & 127;
    int rh = tid >> 7;
    float acc[8];
    float bb = b[c];
#pragma unroll
    for (int i = 0; i < 8; i++) acc[i] = bb;

    for (int kt = 0; kt < IND; kt += 32) {
        __syncthreads();
        // stage W[kt:kt+32, :] (1024 float4)
#pragma unroll
        for (int j = 0; j < 4; j++) {
            int f = tid + j * 256;
            int rr = f >> 5, cc = f & 31;
            reinterpret_cast<float4*>(sW)[f] =
                reinterpret_cast<const float4*>(W)[(kt + rr) * 32 + cc];
        }
        __syncthreads();
#pragma unroll
        for (int d = 0; d < 32; d++) {
            float w = sW[d * 128 + c];
#pragma unroll
            for (int i = 0; i < 8; i++)
                acc[i] = fmaf(sX[(rh * 8 + i) * IND + kt + d], w, acc[i]);
        }
    }
    if (z == 0) {
#pragma unroll
        for (int i = 0; i < 8; i++) g_value[(r0 + rh * 8 + i) * ODIM + c] = acc[i];
    } else {
#pragma unroll
        for (int i = 0; i < 8; i++) outp[(r0 + rh * 8 + i) * (2 * ODIM) + c] = acc[i];
    }
}

// ============================================================
// S1 = x_att @ n_att^T   (1024 x 1024 x 32)
// 64x64 tiles, 256 threads, 4x4 per thread, grid 16x16
// ============================================================
__global__ void __launch_bounds__(256) s1_kernel() {
    __shared__ __align__(16) float sA[32 * 64];  // [d][m]
    __shared__ __align__(16) float sB[32 * 64];  // [d][k]
    int tid = threadIdx.x;
    int bm = blockIdx.x * 64, bk = blockIdx.y * 64;
    // stage with transpose: 64 rows x 32 dims each
#pragma unroll
    for (int j = 0; j < 2; j++) {
        int f = tid + j * 256;          // 0..511 float4 units
        int m = f >> 3, d4 = f & 7;
        float4 va = reinterpret_cast<const float4*>(g_xatt)[(bm + m) * 8 + d4];
        sA[(d4 * 4 + 0) * 64 + m] = va.x;
        sA[(d4 * 4 + 1) * 64 + m] = va.y;
        sA[(d4 * 4 + 2) * 64 + m] = va.z;
        sA[(d4 * 4 + 3) * 64 + m] = va.w;
        float4 vb = reinterpret_cast<const float4*>(g_natt)[(bk + m) * 8 + d4];
        sB[(d4 * 4 + 0) * 64 + m] = vb.x;
        sB[(d4 * 4 + 1) * 64 + m] = vb.y;
        sB[(d4 * 4 + 2) * 64 + m] = vb.z;
        sB[(d4 * 4 + 3) * 64 + m] = vb.w;
    }
    __syncthreads();
    int tx = tid & 15, ty = tid >> 4;
    float acc[4][4];
#pragma unroll
    for (int i = 0; i < 4; i++)
#pragma unroll
        for (int j = 0; j < 4; j++) acc[i][j] = 0.f;
#pragma unroll
    for (int d = 0; d < 32; d++) {
        float4 a4 = *reinterpret_cast<const float4*>(&sA[d * 64 + ty * 4]);
        float4 b4 = *reinterpret_cast<const float4*>(&sB[d * 64 + tx * 4]);
        float a[4] = {a4.x, a4.y, a4.z, a4.w};
        float bvv[4] = {b4.x, b4.y, b4.z, b4.w};
#pragma unroll
        for (int i = 0; i < 4; i++)
#pragma unroll
            for (int j = 0; j < 4; j++)
                acc[i][j] = fmaf(a[i], bvv[j], acc[i][j]);
    }
#pragma unroll
    for (int i = 0; i < 4; i++)
#pragma unroll
        for (int j = 0; j < 4; j++)
            g_s1[(bm + ty * 4 + i) * NN + bk + tx * 4 + j] = acc[i][j];
}

// ============================================================
// per-row: scores (S1 row + gathered edge term) -> leaky -> mask ->
// softmax -> write ws -> weighted edge-embedding sum
// ============================================================
__global__ void __launch_bounds__(256) row_kernel(const int* __restrict__ adj,
                                                  const float* __restrict__ emb) {
    __shared__ int sadj[NN];
    __shared__ float ss[NN];
    __shared__ __align__(16) float sx[32];
    __shared__ float red[8];
    __shared__ __align__(16) float swe[32 * 32];

    int n = blockIdx.x;
    int tid = threadIdx.x;
    for (int k = tid; k < NN; k += 256) {
        sadj[k] = adj[n * NN + k];
        ss[k] = g_s1[n * NN + k];       // node-node term precomputed
    }
    if (tid < 32) sx[tid] = g_xatt[n * 32 + tid];
    __syncthreads();

    int g = tid >> 3, l8 = tid & 7;
    float4 x4 = reinterpret_cast<const float4*>(sx)[l8];
    const float4* proj4 = reinterpret_cast<const float4*>(g_proj);
    const float4* emb4  = reinterpret_cast<const float4*>(emb);

    // ---- phase 1: scores ----
#pragma unroll 4
    for (int it = 0; it < 32; ++it) {
        int k = it * 32 + g;
        int e = sadj[k];
        float4 p = proj4[e * 8 + l8];   // random 128B row gather (L2)
        float part = fmaf(p.x, x4.x, fmaf(p.y, x4.y, fmaf(p.z, x4.z, p.w * x4.w)));
        part += __shfl_xor_sync(0xffffffffu, part, 1);
        part += __shfl_xor_sync(0xffffffffu, part, 2);
        part += __shfl_xor_sync(0xffffffffu, part, 4);
        if (l8 == 0) {
            float s = ss[k] + part;
            s = s > 0.f ? s : 0.01f * s;             // leaky_relu(0.01)
            ss[k] = (e > 0) ? s : -9e15f;            // mask adj>0
        }
    }
    __syncthreads();

    // ---- phase 2: softmax over k ----
    float m = -3.4e38f;
    for (int k = tid; k < NN; k += 256) m = fmaxf(m, ss[k]);
#pragma unroll
    for (int o = 16; o; o >>= 1) m = fmaxf(m, __shfl_xor_sync(0xffffffffu, m, o));
    if ((tid & 31) == 0) red[tid >> 5] = m;
    __syncthreads();
    if (tid == 0) {
        float t = red[0];
        for (int i = 1; i < 8; i++) t = fmaxf(t, red[i]);
        red[0] = t;
    }
    __syncthreads();
    float M = red[0];
    __syncthreads();

    float Z = 0.f;
    for (int k = tid; k < NN; k += 256) {
        float ev = __expf(ss[k] - M);
        ss[k] = ev;
        Z += ev;
    }
#pragma unroll
    for (int o = 16; o; o >>= 1) Z += __shfl_xor_sync(0xffffffffu, Z, o);
    if ((tid & 31) == 0) red[tid >> 5] = Z;
    __syncthreads();
    if (tid == 0) {
        float t = 0.f;
        for (int i = 0; i < 8; i++) t += red[i];
        red[0] = t;
    }
    __syncthreads();
    float inv = 1.f / red[0];
    for (int k = tid; k < NN; k += 256) {
        float w = ss[k] * inv;
        ss[k] = w;
        g_ws[n * NN + k] = w;
    }
    __syncthreads();

    // ---- phase 3: we[n,:] = sum_k ws[k] * edge_emb[adj[n,k],:] ----
    float4 acc = make_float4(0.f, 0.f, 0.f, 0.f);
#pragma unroll 4
    for (int it = 0; it < 32; ++it) {
        int k = it * 32 + g;
        float w = ss[k];
        int e = sadj[k];
        float4 em = emb4[e * 8 + l8];   // second random gather (L2)
        acc.x += w * em.x; acc.y += w * em.y;
        acc.z += w * em.z; acc.w += w * em.w;
    }
    reinterpret_cast<float4*>(swe)[g * 8 + l8] = acc;
    __syncthreads();
    if (tid < 32) {
        float a = 0.f;
        for (int gg = 0; gg < 32; gg++) a += swe[gg * 32 + tid];
        g_we[n * 32 + tid] = a;
    }
}

// ============================================================
// partials of ws @ value (k-split 4), kz=0 also adds we @ Wfe
// 64x64 tiles, 4x4 per thread; grid (16, 2, 4)
// ============================================================
__global__ void __launch_bounds__(256) agg_kernel(const float* __restrict__ Wfe) {
    __shared__ __align__(16) float sA[32 * 64];  // [kk][m]
    __shared__ __align__(16) float sB[32 * 64];  // [kk][c]
    int tid = threadIdx.x;
    int bm = blockIdx.x * 64, bn = blockIdx.y * 64;
    int kz = blockIdx.z;
    int tx = tid & 15, ty = tid >> 4;
    float acc[4][4];
#pragma unroll
    for (int i = 0; i < 4; i++)
#pragma unroll
        for (int j = 0; j < 4; j++) acc[i][j] = 0.f;

    for (int kt = kz * 256; kt < kz * 256 + 256; kt += 32) {
        __syncthreads();
        // stage A = ws[bm:bm+64, kt:kt+32] transposed into [kk][m]
#pragma unroll
        for (int j = 0; j < 2; j++) {
            int f = tid + j * 256;            // 0..511 float4 units
            int mm = f >> 3, c4 = f & 7;
            float4 v = reinterpret_cast<const float4*>(g_ws)[(bm + mm) * 256 + (kt >> 2) + c4];
            sA[(c4 * 4 + 0) * 64 + mm] = v.x;
            sA[(c4 * 4 + 1) * 64 + mm] = v.y;
            sA[(c4 * 4 + 2) * 64 + mm] = v.z;
            sA[(c4 * 4 + 3) * 64 + mm] = v.w;
        }
        // stage B = value[kt:kt+32, bn:bn+64] direct
#pragma unroll
        for (int j = 0; j < 2; j++) {
            int f = tid + j * 256;            // 0..511 float4 units
            int rr = f >> 4, c4 = f & 15;
            reinterpret_cast<float4*>(sB)[f] =
                reinterpret_cast<const float4*>(g_value)[(kt + rr) * 32 + (bn >> 2) + c4];
        }
        __syncthreads();
#pragma unroll
        for (int kk = 0; kk < 32; kk++) {
            float4 a4 = *reinterpret_cast<const float4*>(&sA[kk * 64 + ty * 4]);
            float4 b4 = *reinterpret_cast<const float4*>(&sB[kk * 64 + tx * 4]);
            float a[4] = {a4.x, a4.y, a4.z, a4.w};
            float bvv[4] = {b4.x, b4.y, b4.z, b4.w};
#pragma unroll
            for (int i = 0; i < 4; i++)
#pragma unroll
                for (int j = 0; j < 4; j++)
                    acc[i][j] = fmaf(a[i], bvv[j], acc[i][j]);
        }
    }

    if (kz == 0) {
        // epilogue: + we[bm:bm+64, 0:32] @ Wfe[0:32, bn:bn+64]
        __syncthreads();
#pragma unroll
        for (int j = 0; j < 2; j++) {
            int f = tid + j * 256;
            int mm = f >> 3, c4 = f & 7;
            float4 v = reinterpret_cast<const float4*>(g_we)[(bm + mm) * 8 + c4];
            sA[(c4 * 4 + 0) * 64 + mm] = v.x;
            sA[(c4 * 4 + 1) * 64 + mm] = v.y;
            sA[(c4 * 4 + 2) * 64 + mm] = v.z;
            sA[(c4 * 4 + 3) * 64 + mm] = v.w;
        }
#pragma unroll
        for (int j = 0; j < 2; j++) {
            int f = tid + j * 256;
            int rr = f >> 4, c4 = f & 15;
            reinterpret_cast<float4*>(sB)[f] =
                reinterpret_cast<const float4*>(Wfe)[rr * 32 + (bn >> 2) + c4];
        }
        __syncthreads();
#pragma unroll
        for (int kk = 0; kk < 32; kk++) {
            float4 a4 = *reinterpret_cast<const float4*>(&sA[kk * 64 + ty * 4]);
            float4 b4 = *reinterpret_cast<const float4*>(&sB[kk * 64 + tx * 4]);
            float a[4] = {a4.x, a4.y, a4.z, a4.w};
            float bvv[4] = {b4.x, b4.y, b4.z, b4.w};
#pragma unroll
            for (int i = 0; i < 4; i++)
#pragma unroll
                for (int j = 0; j < 4; j++)
                    acc[i][j] = fmaf(a[i], bvv[j], acc[i][j]);
        }
    }
#pragma unroll
    for (int i = 0; i < 4; i++)
#pragma unroll
        for (int j = 0; j < 4; j++)
            g_part[(kz * NN + bm + ty * 4 + i) * ODIM + bn + tx * 4 + j] = acc[i][j];
}

// ============================================================
// out[n, 128:256] = sum_kz part[kz] + bfe
// ============================================================
__global__ void __launch_bounds__(256) reduce_kernel(const float* __restrict__ bfe,
                                                     float* __restrict__ outp) {
    int idx = blockIdx.x * 256 + threadIdx.x;   // 0..131071
    int n = idx >> 7, c = idx & 127;
    float v = g_part[idx] + g_part[NN * ODIM + idx] +
              g_part[2 * NN * ODIM + idx] + g_part[3 * NN * ODIM + idx] + bfe[c];
    outp[n * (2 * ODIM) + ODIM + c] = v;
}

extern "C" void kernel_launch(void* const* d_in, const int* in_sizes, int n_in,
                              void* d_out, int out_size) {
    const float* x     = (const float*)d_in[0];
    const float* neigh = (const float*)d_in[1];
    const float* emb   = (const float*)d_in[2];
    const int*   adj   = (const int*)d_in[3];
    const float* Wx1 = (const float*)d_in[4];  const float* bx1 = (const float*)d_in[5];
    const float* Wx2 = (const float*)d_in[6];  const float* bx2 = (const float*)d_in[7];
    const float* Wn1 = (const float*)d_in[8];  const float* bn1 = (const float*)d_in[9];
    const float* Wn2 = (const float*)d_in[10]; const float* bn2 = (const float*)d_in[11];
    const float* We  = (const float*)d_in[12]; const float* be  = (const float*)d_in[13];
    const float* Wv  = (const float*)d_in[14]; const float* bv  = (const float*)d_in[15];
    const float* Wfe = (const float*)d_in[16]; const float* bfe = (const float*)d_in[17];
    const float* Wfx = (const float*)d_in[18]; const float* bfx = (const float*)d_in[19];
    float* out = (float*)d_out;

    proj_kernel<<<NE / 32, 256>>>(emb, We, be);
    att_kernel<<<128, 256>>>(x,     Wx1, bx1, Wx2, bx2, 0);
    att_kernel<<<128, 256>>>(neigh, Wn1, bn1, Wn2, bn2, 1);
    s1_kernel<<<dim3(16, 16), 256>>>();
    gemm2_kernel<<<dim3(64, 2), 256>>>(neigh, Wv, bv, x, Wfx, bfx, out);
    row_kernel<<<NN, 256>>>(adj, emb);
    agg_kernel<<<dim3(16, 2, 4), 256>>>(Wfe);
    reduce_kernel<<<512, 256>>>(bfe, out);
}

// round 4
// speedup vs baseline: 2.1677x; 1.1733x over previous
#include <cuda_runtime.h>
#include <math.h>

#define NN   1024
#define IND  256
#define ED   32
#define HID  32
#define ODIM 128
#define NE   100000

#define NB_PROJ (NE / 32)        // 3125
#define NB_ATT  128              // per att pass (8 rows/block)
#define NB_GEMM 64               // per gemm2 z-slice

// ---- scratch (device globals; no allocation allowed) ----
__device__ float g_proj[NE * ED];        // tanh(edge_emb @ We + be)
__device__ float g_xatt[NN * HID];
__device__ float g_natt[NN * HID];
__device__ float g_value[NN * ODIM];     // neigh @ Wv + bv
__device__ float g_s1[NN * NN];          // x_att @ n_att^T
__device__ float g_ws[NN * NN];          // softmax weights
__device__ float g_we[NN * ED];          // ws-weighted edge embeddings
__device__ float g_part[4 * NN * ODIM];  // ksplit partials of ws@value

// ============================================================
// device helpers (operate on a shared scratch buffer)
// ============================================================
__device__ __forceinline__ void do_proj(float* sm, int blk,
                                        const float* __restrict__ emb,
                                        const float* __restrict__ We,
                                        const float* __restrict__ be) {
    float* sW = sm;               // 1024
    float* sb = sm + 1024;        // 32
    float* sx = sm + 1024 + 64;   // 1024 (keep 16B alignment)
    int tid = threadIdx.x;
    for (int i = tid; i < 1024; i += 256) sW[i] = We[i];
    if (tid < 32) sb[tid] = be[tid];
    int rows0 = blk * 32;
    reinterpret_cast<float4*>(sx)[tid] =
        reinterpret_cast<const float4*>(emb)[rows0 * 8 + tid];
    __syncthreads();
    int col = tid & 31;
    int r0 = (tid >> 5) * 4;
    float acc0 = sb[col], acc1 = acc0, acc2 = acc0, acc3 = acc0;
#pragma unroll
    for (int d = 0; d < 32; d++) {
        float w = sW[d * 32 + col];
        acc0 = fmaf(sx[(r0 + 0) * 32 + d], w, acc0);
        acc1 = fmaf(sx[(r0 + 1) * 32 + d], w, acc1);
        acc2 = fmaf(sx[(r0 + 2) * 32 + d], w, acc2);
        acc3 = fmaf(sx[(r0 + 3) * 32 + d], w, acc3);
    }
    g_proj[(rows0 + r0 + 0) * 32 + col] = tanhf(acc0);
    g_proj[(rows0 + r0 + 1) * 32 + col] = tanhf(acc1);
    g_proj[(rows0 + r0 + 2) * 32 + col] = tanhf(acc2);
    g_proj[(rows0 + r0 + 3) * 32 + col] = tanhf(acc3);
}

__device__ __forceinline__ void do_att(float* sm, int blk,
                                       const float* __restrict__ X,
                                       const float* __restrict__ W1,
                                       const float* __restrict__ b1,
                                       const float* __restrict__ W2,
                                       const float* __restrict__ b2,
                                       float* __restrict__ dst) {
    float* sx = sm;   // 8 * 256
    int warp = threadIdx.x >> 5, lane = threadIdx.x & 31;
    int row = blk * 8 + warp;
    for (int d = lane; d < IND; d += 32) sx[warp * IND + d] = X[row * IND + d];
    __syncwarp();
    float acc = b1[lane];
#pragma unroll 8
    for (int d = 0; d < IND; d++)
        acc = fmaf(sx[warp * IND + d], W1[d * 32 + lane], acc);
    float h = tanhf(acc);
    float a2 = b2[lane];
#pragma unroll
    for (int j = 0; j < 32; j++)
        a2 = fmaf(__shfl_sync(0xffffffffu, h, j), W2[j * 32 + lane], a2);
    dst[row * 32 + lane] = a2;
}

__device__ __forceinline__ void do_gemm2(float* sm, int blk, int z,
                                         const float* __restrict__ X,
                                         const float* __restrict__ W,
                                         const float* __restrict__ b,
                                         float* __restrict__ outp) {
    float* sX = sm;          // 16 * 256 = 4096
    float* sW = sm + 4096;   // 32 * 128 = 4096
    int tid = threadIdx.x;
    int r0 = blk * 16;
#pragma unroll
    for (int j = 0; j < 4; j++) {
        int f = tid + j * 256;
        int r = f >> 6, c4 = f & 63;
        reinterpret_cast<float4*>(sX)[f] =
            reinterpret_cast<const float4*>(X)[(r0 + r) * 64 + c4];
    }
    int c = tid & 127;
    int rh = tid >> 7;
    float acc[8];
    float bb = b[c];
#pragma unroll
    for (int i = 0; i < 8; i++) acc[i] = bb;

    for (int kt = 0; kt < IND; kt += 32) {
        __syncthreads();
#pragma unroll
        for (int j = 0; j < 4; j++) {
            int f = tid + j * 256;
            int rr = f >> 5, cc = f & 31;
            reinterpret_cast<float4*>(sW)[f] =
                reinterpret_cast<const float4*>(W)[(kt + rr) * 32 + cc];
        }
        __syncthreads();
#pragma unroll
        for (int d = 0; d < 32; d++) {
            float w = sW[d * 128 + c];
#pragma unroll
            for (int i = 0; i < 8; i++)
                acc[i] = fmaf(sX[(rh * 8 + i) * IND + kt + d], w, acc[i]);
        }
    }
    if (z == 0) {
#pragma unroll
        for (int i = 0; i < 8; i++) g_value[(r0 + rh * 8 + i) * ODIM + c] = acc[i];
    } else {
#pragma unroll
        for (int i = 0; i < 8; i++) outp[(r0 + rh * 8 + i) * (2 * ODIM) + c] = acc[i];
    }
}

// ============================================================
// mega-kernel 1: all work independent of each other
//   [0, NB_PROJ)                 proj
//   [NB_PROJ, +128)              att on x    -> g_xatt
//   [NB_PROJ+128, +128)          att on neigh-> g_natt
//   [NB_PROJ+256, +128)          gemm2 (z = local/64)
// ============================================================
__global__ void __launch_bounds__(256) pre_kernel(
    const float* __restrict__ emb, const float* __restrict__ We,
    const float* __restrict__ be,
    const float* __restrict__ x, const float* __restrict__ Wx1,
    const float* __restrict__ bx1, const float* __restrict__ Wx2,
    const float* __restrict__ bx2,
    const float* __restrict__ neigh, const float* __restrict__ Wn1,
    const float* __restrict__ bn1, const float* __restrict__ Wn2,
    const float* __restrict__ bn2,
    const float* __restrict__ Wv, const float* __restrict__ bv,
    const float* __restrict__ Wfx, const float* __restrict__ bfx,
    float* __restrict__ outp) {
    __shared__ __align__(16) float sm[8192];   // 32 KB, aliased per branch
    int bid = blockIdx.x;
    if (bid < NB_PROJ) {
        do_proj(sm, bid, emb, We, be);
    } else if (bid < NB_PROJ + NB_ATT) {
        do_att(sm, bid - NB_PROJ, x, Wx1, bx1, Wx2, bx2, g_xatt);
    } else if (bid < NB_PROJ + 2 * NB_ATT) {
        do_att(sm, bid - NB_PROJ - NB_ATT, neigh, Wn1, bn1, Wn2, bn2, g_natt);
    } else {
        int local = bid - NB_PROJ - 2 * NB_ATT;
        int z = local >> 6;           // 0..1
        int blk = local & 63;
        if (z == 0) do_gemm2(sm, blk, 0, neigh, Wv, bv, nullptr);
        else        do_gemm2(sm, blk, 1, x, Wfx, bfx, outp);
    }
}

// ============================================================
// S1 = x_att @ n_att^T   (1024 x 1024 x 32)
// 64x32 tiles, 256 threads, 4x2 per thread, grid (16, 32) = 512 blocks
// ============================================================
__global__ void __launch_bounds__(256) s1_kernel() {
    __shared__ __align__(16) float sA[32 * 64];  // [d][m]
    __shared__ __align__(16) float sB[32 * 32];  // [d][k]
    int tid = threadIdx.x;
    int bm = blockIdx.x * 64, bk = blockIdx.y * 32;
#pragma unroll
    for (int j = 0; j < 2; j++) {
        int f = tid + j * 256;          // 0..511 float4 units
        int m = f >> 3, d4 = f & 7;
        float4 va = reinterpret_cast<const float4*>(g_xatt)[(bm + m) * 8 + d4];
        sA[(d4 * 4 + 0) * 64 + m] = va.x;
        sA[(d4 * 4 + 1) * 64 + m] = va.y;
        sA[(d4 * 4 + 2) * 64 + m] = va.z;
        sA[(d4 * 4 + 3) * 64 + m] = va.w;
    }
    {
        int m = tid >> 3, d4 = tid & 7;   // 32 rows x 8 float4
        float4 vb = reinterpret_cast<const float4*>(g_natt)[(bk + m) * 8 + d4];
        sB[(d4 * 4 + 0) * 32 + m] = vb.x;
        sB[(d4 * 4 + 1) * 32 + m] = vb.y;
        sB[(d4 * 4 + 2) * 32 + m] = vb.z;
        sB[(d4 * 4 + 3) * 32 + m] = vb.w;
    }
    __syncthreads();
    int tx = tid & 15, ty = tid >> 4;
    float acc[4][2];
#pragma unroll
    for (int i = 0; i < 4; i++) { acc[i][0] = 0.f; acc[i][1] = 0.f; }
#pragma unroll
    for (int d = 0; d < 32; d++) {
        float4 a4 = *reinterpret_cast<const float4*>(&sA[d * 64 + ty * 4]);
        float b0 = sB[d * 32 + tx * 2];
        float b1 = sB[d * 32 + tx * 2 + 1];
        float a[4] = {a4.x, a4.y, a4.z, a4.w};
#pragma unroll
        for (int i = 0; i < 4; i++) {
            acc[i][0] = fmaf(a[i], b0, acc[i][0]);
            acc[i][1] = fmaf(a[i], b1, acc[i][1]);
        }
    }
#pragma unroll
    for (int i = 0; i < 4; i++) {
        g_s1[(bm + ty * 4 + i) * NN + bk + tx * 2]     = acc[i][0];
        g_s1[(bm + ty * 4 + i) * NN + bk + tx * 2 + 1] = acc[i][1];
    }
}

// ============================================================
// per-row: scores (S1 row + gathered edge term) -> leaky -> mask ->
// softmax -> write ws -> weighted edge-embedding sum
// ============================================================
__global__ void __launch_bounds__(256) row_kernel(const int* __restrict__ adj,
                                                  const float* __restrict__ emb) {
    __shared__ int sadj[NN];
    __shared__ float ss[NN];
    __shared__ __align__(16) float sx[32];
    __shared__ float red[8];
    __shared__ __align__(16) float swe[32 * 32];

    int n = blockIdx.x;
    int tid = threadIdx.x;
    for (int k = tid; k < NN; k += 256) {
        sadj[k] = adj[n * NN + k];
        ss[k] = g_s1[n * NN + k];       // node-node term precomputed
    }
    if (tid < 32) sx[tid] = g_xatt[n * 32 + tid];
    __syncthreads();

    int g = tid >> 3, l8 = tid & 7;
    float4 x4 = reinterpret_cast<const float4*>(sx)[l8];
    const float4* proj4 = reinterpret_cast<const float4*>(g_proj);
    const float4* emb4  = reinterpret_cast<const float4*>(emb);

    // ---- phase 1: scores ----
#pragma unroll 4
    for (int it = 0; it < 32; ++it) {
        int k = it * 32 + g;
        int e = sadj[k];
        float4 p = proj4[e * 8 + l8];   // random 128B row gather (L2)
        float part = fmaf(p.x, x4.x, fmaf(p.y, x4.y, fmaf(p.z, x4.z, p.w * x4.w)));
        part += __shfl_xor_sync(0xffffffffu, part, 1);
        part += __shfl_xor_sync(0xffffffffu, part, 2);
        part += __shfl_xor_sync(0xffffffffu, part, 4);
        if (l8 == 0) {
            float s = ss[k] + part;
            s = s > 0.f ? s : 0.01f * s;             // leaky_relu(0.01)
            ss[k] = (e > 0) ? s : -9e15f;            // mask adj>0
        }
    }
    __syncthreads();

    // ---- phase 2: softmax over k ----
    float m = -3.4e38f;
    for (int k = tid; k < NN; k += 256) m = fmaxf(m, ss[k]);
#pragma unroll
    for (int o = 16; o; o >>= 1) m = fmaxf(m, __shfl_xor_sync(0xffffffffu, m, o));
    if ((tid & 31) == 0) red[tid >> 5] = m;
    __syncthreads();
    if (tid == 0) {
        float t = red[0];
        for (int i = 1; i < 8; i++) t = fmaxf(t, red[i]);
        red[0] = t;
    }
    __syncthreads();
    float M = red[0];
    __syncthreads();

    float Z = 0.f;
    for (int k = tid; k < NN; k += 256) {
        float ev = __expf(ss[k] - M);
        ss[k] = ev;
        Z += ev;
    }
#pragma unroll
    for (int o = 16; o; o >>= 1) Z += __shfl_xor_sync(0xffffffffu, Z, o);
    if ((tid & 31) == 0) red[tid >> 5] = Z;
    __syncthreads();
    if (tid == 0) {
        float t = 0.f;
        for (int i = 0; i < 8; i++) t += red[i];
        red[0] = t;
    }
    __syncthreads();
    float inv = 1.f / red[0];
    for (int k = tid; k < NN; k += 256) {
        float w = ss[k] * inv;
        ss[k] = w;
        g_ws[n * NN + k] = w;
    }
    __syncthreads();

    // ---- phase 3: we[n,:] = sum_k ws[k] * edge_emb[adj[n,k],:] ----
    float4 acc = make_float4(0.f, 0.f, 0.f, 0.f);
#pragma unroll 4
    for (int it = 0; it < 32; ++it) {
        int k = it * 32 + g;
        float w = ss[k];
        int e = sadj[k];
        float4 em = emb4[e * 8 + l8];   // second random gather (L2)
        acc.x += w * em.x; acc.y += w * em.y;
        acc.z += w * em.z; acc.w += w * em.w;
    }
    reinterpret_cast<float4*>(swe)[g * 8 + l8] = acc;
    __syncthreads();
    if (tid < 32) {
        float a = 0.f;
        for (int gg = 0; gg < 32; gg++) a += swe[gg * 32 + tid];
        g_we[n * 32 + tid] = a;
    }
}

// ============================================================
// partials of ws @ value (k-split 4), kz=0 also adds we @ Wfe
// 64x64 tiles, 4x4 per thread; grid (16, 2, 4)
// ============================================================
__global__ void __launch_bounds__(256) agg_kernel(const float* __restrict__ Wfe) {
    __shared__ __align__(16) float sA[32 * 64];  // [kk][m]
    __shared__ __align__(16) float sB[32 * 64];  // [kk][c]
    int tid = threadIdx.x;
    int bm = blockIdx.x * 64, bn = blockIdx.y * 64;
    int kz = blockIdx.z;
    int tx = tid & 15, ty = tid >> 4;
    float acc[4][4];
#pragma unroll
    for (int i = 0; i < 4; i++)
#pragma unroll
        for (int j = 0; j < 4; j++) acc[i][j] = 0.f;

    for (int kt = kz * 256; kt < kz * 256 + 256; kt += 32) {
        __syncthreads();
#pragma unroll
        for (int j = 0; j < 2; j++) {
            int f = tid + j * 256;            // 0..511 float4 units
            int mm = f >> 3, c4 = f & 7;
            float4 v = reinterpret_cast<const float4*>(g_ws)[(bm + mm) * 256 + (kt >> 2) + c4];
            sA[(c4 * 4 + 0) * 64 + mm] = v.x;
            sA[(c4 * 4 + 1) * 64 + mm] = v.y;
            sA[(c4 * 4 + 2) * 64 + mm] = v.z;
            sA[(c4 * 4 + 3) * 64 + mm] = v.w;
        }
#pragma unroll
        for (int j = 0; j < 2; j++) {
            int f = tid + j * 256;            // 0..511 float4 units
            int rr = f >> 4, c4 = f & 15;
            reinterpret_cast<float4*>(sB)[f] =
                reinterpret_cast<const float4*>(g_value)[(kt + rr) * 32 + (bn >> 2) + c4];
        }
        __syncthreads();
#pragma unroll
        for (int kk = 0; kk < 32; kk++) {
            float4 a4 = *reinterpret_cast<const float4*>(&sA[kk * 64 + ty * 4]);
            float4 b4 = *reinterpret_cast<const float4*>(&sB[kk * 64 + tx * 4]);
            float a[4] = {a4.x, a4.y, a4.z, a4.w};
            float bvv[4] = {b4.x, b4.y, b4.z, b4.w};
#pragma unroll
            for (int i = 0; i < 4; i++)
#pragma unroll
                for (int j = 0; j < 4; j++)
                    acc[i][j] = fmaf(a[i], bvv[j], acc[i][j]);
        }
    }

    if (kz == 0) {
        // epilogue: + we[bm:bm+64, 0:32] @ Wfe[0:32, bn:bn+64]
        __syncthreads();
#pragma unroll
        for (int j = 0; j < 2; j++) {
            int f = tid + j * 256;
            int mm = f >> 3, c4 = f & 7;
            float4 v = reinterpret_cast<const float4*>(g_we)[(bm + mm) * 8 + c4];
            sA[(c4 * 4 + 0) * 64 + mm] = v.x;
            sA[(c4 * 4 + 1) * 64 + mm] = v.y;
            sA[(c4 * 4 + 2) * 64 + mm] = v.z;
            sA[(c4 * 4 + 3) * 64 + mm] = v.w;
        }
#pragma unroll
        for (int j = 0; j < 2; j++) {
            int f = tid + j * 256;
            int rr = f >> 4, c4 = f & 15;
            reinterpret_cast<float4*>(sB)[f] =
                reinterpret_cast<const float4*>(Wfe)[rr * 32 + (bn >> 2) + c4];
        }
        __syncthreads();
#pragma unroll
        for (int kk = 0; kk < 32; kk++) {
            float4 a4 = *reinterpret_cast<const float4*>(&sA[kk * 64 + ty * 4]);
            float4 b4 = *reinterpret_cast<const float4*>(&sB[kk * 64 + tx * 4]);
            float a[4] = {a4.x, a4.y, a4.z, a4.w};
            float bvv[4] = {b4.x, b4.y, b4.z, b4.w};
#pragma unroll
            for (int i = 0; i < 4; i++)
#pragma unroll
                for (int j = 0; j < 4; j++)
                    acc[i][j] = fmaf(a[i], bvv[j], acc[i][j]);
        }
    }
#pragma unroll
    for (int i = 0; i < 4; i++)
#pragma unroll
        for (int j = 0; j < 4; j++)
            g_part[(kz * NN + bm + ty * 4 + i) * ODIM + bn + tx * 4 + j] = acc[i][j];
}

// ============================================================
// out[n, 128:256] = sum_kz part[kz] + bfe
// ============================================================
__global__ void __launch_bounds__(256) reduce_kernel(const float* __restrict__ bfe,
                                                     float* __restrict__ outp) {
    int idx = blockIdx.x * 256 + threadIdx.x;   // 0..131071
    int n = idx >> 7, c = idx & 127;
    float v = g_part[idx] + g_part[NN * ODIM + idx] +
              g_part[2 * NN * ODIM + idx] + g_part[3 * NN * ODIM + idx] + bfe[c];
    outp[n * (2 * ODIM) + ODIM + c] = v;
}

extern "C" void kernel_launch(void* const* d_in, const int* in_sizes, int n_in,
                              void* d_out, int out_size) {
    const float* x     = (const float*)d_in[0];
    const float* neigh = (const float*)d_in[1];
    const float* emb   = (const float*)d_in[2];
    const int*   adj   = (const int*)d_in[3];
    const float* Wx1 = (const float*)d_in[4];  const float* bx1 = (const float*)d_in[5];
    const float* Wx2 = (const float*)d_in[6];  const float* bx2 = (const float*)d_in[7];
    const float* Wn1 = (const float*)d_in[8];  const float* bn1 = (const float*)d_in[9];
    const float* Wn2 = (const float*)d_in[10]; const float* bn2 = (const float*)d_in[11];
    const float* We  = (const float*)d_in[12]; const float* be  = (const float*)d_in[13];
    const float* Wv  = (const float*)d_in[14]; const float* bv  = (const float*)d_in[15];
    const float* Wfe = (const float*)d_in[16]; const float* bfe = (const float*)d_in[17];
    const float* Wfx = (const float*)d_in[18]; const float* bfx = (const float*)d_in[19];
    float* out = (float*)d_out;

    pre_kernel<<<NB_PROJ + 2 * NB_ATT + 2 * NB_GEMM, 256>>>(
        emb, We, be,
        x, Wx1, bx1, Wx2, bx2,
        neigh, Wn1, bn1, Wn2, bn2,
        Wv, bv, Wfx, bfx, out);
    s1_kernel<<<dim3(16, 32), 256>>>();
    row_kernel<<<NN, 256>>>(adj, emb);
    agg_kernel<<<dim3(16, 2, 4), 256>>>(Wfe);
    reduce_kernel<<<512, 256>>>(bfe, out);
}

// round 5
// speedup vs baseline: 2.2336x; 1.0304x over previous
#include <cuda_runtime.h>
#include <math.h>

#define NN   1024
#define IND  256
#define ED   32
#define HID  32
#define ODIM 128
#define NE   100000

#define NB_PROJ (NE / 32)        // 3125
#define NB_ATT  128              // per att pass (8 rows/block)
#define NB_GEMM 64               // per gemm2 z-slice
#define KSPLIT  8                // agg k-split

// ---- scratch (device globals; no allocation allowed) ----
__device__ float g_proj[NE * ED];        // tanh(edge_emb @ We + be)
__device__ float g_xatt[NN * HID];
__device__ float g_natt[NN * HID];
__device__ float g_value[NN * ODIM];     // neigh @ Wv + bv
__device__ float g_s1[NN * NN];          // x_att @ n_att^T
__device__ float g_ws[NN * NN];          // softmax weights
__device__ float g_we[NN * ED];          // ws-weighted edge embeddings
__device__ float g_part[KSPLIT * NN * ODIM];  // ksplit partials of ws@value

// ============================================================
// device helpers (operate on a shared scratch buffer)
// ============================================================
__device__ __forceinline__ void do_proj(float* sm, int blk,
                                        const float* __restrict__ emb,
                                        const float* __restrict__ We,
                                        const float* __restrict__ be) {
    float* sW = sm;               // 1024
    float* sb = sm + 1024;        // 32
    float* sx = sm + 1024 + 64;   // 1024 (keep 16B alignment)
    int tid = threadIdx.x;
    for (int i = tid; i < 1024; i += 256) sW[i] = We[i];
    if (tid < 32) sb[tid] = be[tid];
    int rows0 = blk * 32;
    reinterpret_cast<float4*>(sx)[tid] =
        reinterpret_cast<const float4*>(emb)[rows0 * 8 + tid];
    __syncthreads();
    int col = tid & 31;
    int r0 = (tid >> 5) * 4;
    float acc0 = sb[col], acc1 = acc0, acc2 = acc0, acc3 = acc0;
#pragma unroll
    for (int d = 0; d < 32; d++) {
        float w = sW[d * 32 + col];
        acc0 = fmaf(sx[(r0 + 0) * 32 + d], w, acc0);
        acc1 = fmaf(sx[(r0 + 1) * 32 + d], w, acc1);
        acc2 = fmaf(sx[(r0 + 2) * 32 + d], w, acc2);
        acc3 = fmaf(sx[(r0 + 3) * 32 + d], w, acc3);
    }
    g_proj[(rows0 + r0 + 0) * 32 + col] = tanhf(acc0);
    g_proj[(rows0 + r0 + 1) * 32 + col] = tanhf(acc1);
    g_proj[(rows0 + r0 + 2) * 32 + col] = tanhf(acc2);
    g_proj[(rows0 + r0 + 3) * 32 + col] = tanhf(acc3);
}

__device__ __forceinline__ void do_att(float* sm, int blk,
                                       const float* __restrict__ X,
                                       const float* __restrict__ W1,
                                       const float* __restrict__ b1,
                                       const float* __restrict__ W2,
                                       const float* __restrict__ b2,
                                       float* __restrict__ dst) {
    float* sx = sm;   // 8 * 256
    int warp = threadIdx.x >> 5, lane = threadIdx.x & 31;
    int row = blk * 8 + warp;
    for (int d = lane; d < IND; d += 32) sx[warp * IND + d] = X[row * IND + d];
    __syncwarp();
    float acc = b1[lane];
#pragma unroll 8
    for (int d = 0; d < IND; d++)
        acc = fmaf(sx[warp * IND + d], W1[d * 32 + lane], acc);
    float h = tanhf(acc);
    float a2 = b2[lane];
#pragma unroll
    for (int j = 0; j < 32; j++)
        a2 = fmaf(__shfl_sync(0xffffffffu, h, j), W2[j * 32 + lane], a2);
    dst[row * 32 + lane] = a2;
}

__device__ __forceinline__ void do_gemm2(float* sm, int blk, int z,
                                         const float* __restrict__ X,
                                         const float* __restrict__ W,
                                         const float* __restrict__ b,
                                         float* __restrict__ outp) {
    float* sX = sm;          // 16 * 256 = 4096
    float* sW = sm + 4096;   // 32 * 128 = 4096
    int tid = threadIdx.x;
    int r0 = blk * 16;
#pragma unroll
    for (int j = 0; j < 4; j++) {
        int f = tid + j * 256;
        int r = f >> 6, c4 = f & 63;
        reinterpret_cast<float4*>(sX)[f] =
            reinterpret_cast<const float4*>(X)[(r0 + r) * 64 + c4];
    }
    int c = tid & 127;
    int rh = tid >> 7;
    float acc[8];
    float bb = b[c];
#pragma unroll
    for (int i = 0; i < 8; i++) acc[i] = bb;

    for (int kt = 0; kt < IND; kt += 32) {
        __syncthreads();
#pragma unroll
        for (int j = 0; j < 4; j++) {
            int f = tid + j * 256;
            int rr = f >> 5, cc = f & 31;
            reinterpret_cast<float4*>(sW)[f] =
                reinterpret_cast<const float4*>(W)[(kt + rr) * 32 + cc];
        }
        __syncthreads();
#pragma unroll
        for (int d = 0; d < 32; d++) {
            float w = sW[d * 128 + c];
#pragma unroll
            for (int i = 0; i < 8; i++)
                acc[i] = fmaf(sX[(rh * 8 + i) * IND + kt + d], w, acc[i]);
        }
    }
    if (z == 0) {
#pragma unroll
        for (int i = 0; i < 8; i++) g_value[(r0 + rh * 8 + i) * ODIM + c] = acc[i];
    } else {
#pragma unroll
        for (int i = 0; i < 8; i++) outp[(r0 + rh * 8 + i) * (2 * ODIM) + c] = acc[i];
    }
}

// ============================================================
// mega-kernel 1: all work independent of each other
// ============================================================
__global__ void __launch_bounds__(256) pre_kernel(
    const float* __restrict__ emb, const float* __restrict__ We,
    const float* __restrict__ be,
    const float* __restrict__ x, const float* __restrict__ Wx1,
    const float* __restrict__ bx1, const float* __restrict__ Wx2,
    const float* __restrict__ bx2,
    const float* __restrict__ neigh, const float* __restrict__ Wn1,
    const float* __restrict__ bn1, const float* __restrict__ Wn2,
    const float* __restrict__ bn2,
    const float* __restrict__ Wv, const float* __restrict__ bv,
    const float* __restrict__ Wfx, const float* __restrict__ bfx,
    float* __restrict__ outp) {
    __shared__ __align__(16) float sm[8192];   // 32 KB, aliased per branch
    int bid = blockIdx.x;
    if (bid < NB_PROJ) {
        do_proj(sm, bid, emb, We, be);
    } else if (bid < NB_PROJ + NB_ATT) {
        do_att(sm, bid - NB_PROJ, x, Wx1, bx1, Wx2, bx2, g_xatt);
    } else if (bid < NB_PROJ + 2 * NB_ATT) {
        do_att(sm, bid - NB_PROJ - NB_ATT, neigh, Wn1, bn1, Wn2, bn2, g_natt);
    } else {
        int local = bid - NB_PROJ - 2 * NB_ATT;
        int z = local >> 6;           // 0..1
        int blk = local & 63;
        if (z == 0) do_gemm2(sm, blk, 0, neigh, Wv, bv, nullptr);
        else        do_gemm2(sm, blk, 1, x, Wfx, bfx, outp);
    }
}

// ============================================================
// S1 = x_att @ n_att^T   (1024 x 1024 x 32)
// 64x32 tiles, 256 threads, 4x2 per thread, grid (16, 32) = 512 blocks
// ============================================================
__global__ void __launch_bounds__(256) s1_kernel() {
    __shared__ __align__(16) float sA[32 * 64];  // [d][m]
    __shared__ __align__(16) float sB[32 * 32];  // [d][k]
    int tid = threadIdx.x;
    int bm = blockIdx.x * 64, bk = blockIdx.y * 32;
#pragma unroll
    for (int j = 0; j < 2; j++) {
        int f = tid + j * 256;          // 0..511 float4 units
        int m = f >> 3, d4 = f & 7;
        float4 va = reinterpret_cast<const float4*>(g_xatt)[(bm + m) * 8 + d4];
        sA[(d4 * 4 + 0) * 64 + m] = va.x;
        sA[(d4 * 4 + 1) * 64 + m] = va.y;
        sA[(d4 * 4 + 2) * 64 + m] = va.z;
        sA[(d4 * 4 + 3) * 64 + m] = va.w;
    }
    {
        int m = tid >> 3, d4 = tid & 7;   // 32 rows x 8 float4
        float4 vb = reinterpret_cast<const float4*>(g_natt)[(bk + m) * 8 + d4];
        sB[(d4 * 4 + 0) * 32 + m] = vb.x;
        sB[(d4 * 4 + 1) * 32 + m] = vb.y;
        sB[(d4 * 4 + 2) * 32 + m] = vb.z;
        sB[(d4 * 4 + 3) * 32 + m] = vb.w;
    }
    __syncthreads();
    int tx = tid & 15, ty = tid >> 4;
    float acc[4][2];
#pragma unroll
    for (int i = 0; i < 4; i++) { acc[i][0] = 0.f; acc[i][1] = 0.f; }
#pragma unroll
    for (int d = 0; d < 32; d++) {
        float4 a4 = *reinterpret_cast<const float4*>(&sA[d * 64 + ty * 4]);
        float b0 = sB[d * 32 + tx * 2];
        float b1 = sB[d * 32 + tx * 2 + 1];
        float a[4] = {a4.x, a4.y, a4.z, a4.w};
#pragma unroll
        for (int i = 0; i < 4; i++) {
            acc[i][0] = fmaf(a[i], b0, acc[i][0]);
            acc[i][1] = fmaf(a[i], b1, acc[i][1]);
        }
    }
#pragma unroll
    for (int i = 0; i < 4; i++) {
        g_s1[(bm + ty * 4 + i) * NN + bk + tx * 2]     = acc[i][0];
        g_s1[(bm + ty * 4 + i) * NN + bk + tx * 2 + 1] = acc[i][1];
    }
}

// ============================================================
// per-row: scores (S1 row + gathered edge term) -> leaky -> mask ->
// softmax -> write ws -> weighted edge-embedding sum
// ============================================================
__global__ void __launch_bounds__(256) row_kernel(const int* __restrict__ adj,
                                                  const float* __restrict__ emb) {
    __shared__ int sadj[NN];
    __shared__ float ss[NN];
    __shared__ __align__(16) float sx[32];
    __shared__ float red[8];
    __shared__ __align__(16) float swe[32 * 32];

    int n = blockIdx.x;
    int tid = threadIdx.x;
    for (int k = tid; k < NN; k += 256) {
        sadj[k] = adj[n * NN + k];
        ss[k] = g_s1[n * NN + k];       // node-node term precomputed
    }
    if (tid < 32) sx[tid] = g_xatt[n * 32 + tid];
    __syncthreads();

    int g = tid >> 3, l8 = tid & 7;
    float4 x4 = reinterpret_cast<const float4*>(sx)[l8];
    const float4* proj4 = reinterpret_cast<const float4*>(g_proj);
    const float4* emb4  = reinterpret_cast<const float4*>(emb);

    // ---- phase 1: scores ----
#pragma unroll 4
    for (int it = 0; it < 32; ++it) {
        int k = it * 32 + g;
        int e = sadj[k];
        float4 p = proj4[e * 8 + l8];   // random 128B row gather (L2)
        float part = fmaf(p.x, x4.x, fmaf(p.y, x4.y, fmaf(p.z, x4.z, p.w * x4.w)));
        part += __shfl_xor_sync(0xffffffffu, part, 1);
        part += __shfl_xor_sync(0xffffffffu, part, 2);
        part += __shfl_xor_sync(0xffffffffu, part, 4);
        if (l8 == 0) {
            float s = ss[k] + part;
            s = s > 0.f ? s : 0.01f * s;             // leaky_relu(0.01)
            ss[k] = (e > 0) ? s : -9e15f;            // mask adj>0
        }
    }
    __syncthreads();

    // ---- phase 2: softmax over k ----
    float m = -3.4e38f;
    for (int k = tid; k < NN; k += 256) m = fmaxf(m, ss[k]);
#pragma unroll
    for (int o = 16; o; o >>= 1) m = fmaxf(m, __shfl_xor_sync(0xffffffffu, m, o));
    if ((tid & 31) == 0) red[tid >> 5] = m;
    __syncthreads();
    if (tid == 0) {
        float t = red[0];
        for (int i = 1; i < 8; i++) t = fmaxf(t, red[i]);
        red[0] = t;
    }
    __syncthreads();
    float M = red[0];
    __syncthreads();

    float Z = 0.f;
    for (int k = tid; k < NN; k += 256) {
        float ev = __expf(ss[k] - M);
        ss[k] = ev;
        Z += ev;
    }
#pragma unroll
    for (int o = 16; o; o >>= 1) Z += __shfl_xor_sync(0xffffffffu, Z, o);
    if ((tid & 31) == 0) red[tid >> 5] = Z;
    __syncthreads();
    if (tid == 0) {
        float t = 0.f;
        for (int i = 0; i < 8; i++) t += red[i];
        red[0] = t;
    }
    __syncthreads();
    float inv = 1.f / red[0];
    for (int k = tid; k < NN; k += 256) {
        float w = ss[k] * inv;
        ss[k] = w;
        g_ws[n * NN + k] = w;
    }
    __syncthreads();

    // ---- phase 3: we[n,:] = sum_k ws[k] * edge_emb[adj[n,k],:] ----
    float4 acc = make_float4(0.f, 0.f, 0.f, 0.f);
#pragma unroll 4
    for (int it = 0; it < 32; ++it) {
        int k = it * 32 + g;
        float w = ss[k];
        int e = sadj[k];
        float4 em = emb4[e * 8 + l8];   // second random gather (L2)
        acc.x += w * em.x; acc.y += w * em.y;
        acc.z += w * em.z; acc.w += w * em.w;
    }
    reinterpret_cast<float4*>(swe)[g * 8 + l8] = acc;
    __syncthreads();
    if (tid < 32) {
        float a = 0.f;
        for (int gg = 0; gg < 32; gg++) a += swe[gg * 32 + tid];
        g_we[n * 32 + tid] = a;
    }
}

// ============================================================
// partials of ws @ value (k-split KSPLIT=8), kz=0 also adds we @ Wfe
// 64x64 tiles, 4x4 per thread; grid (16, 2, 8) = 256 blocks
// ============================================================
__global__ void __launch_bounds__(256) agg_kernel(const float* __restrict__ Wfe) {
    __shared__ __align__(16) float sA[32 * 64];  // [kk][m]
    __shared__ __align__(16) float sB[32 * 64];  // [kk][c]
    int tid = threadIdx.x;
    int bm = blockIdx.x * 64, bn = blockIdx.y * 64;
    int kz = blockIdx.z;
    int tx = tid & 15, ty = tid >> 4;
    float acc[4][4];
#pragma unroll
    for (int i = 0; i < 4; i++)
#pragma unroll
        for (int j = 0; j < 4; j++) acc[i][j] = 0.f;

    const int KCH = NN / KSPLIT;   // 128
    for (int kt = kz * KCH; kt < kz * KCH + KCH; kt += 32) {
        __syncthreads();
#pragma unroll
        for (int j = 0; j < 2; j++) {
            int f = tid + j * 256;            // 0..511 float4 units
            int mm = f >> 3, c4 = f & 7;
            float4 v = reinterpret_cast<const float4*>(g_ws)[(bm + mm) * 256 + (kt >> 2) + c4];
            sA[(c4 * 4 + 0) * 64 + mm] = v.x;
            sA[(c4 * 4 + 1) * 64 + mm] = v.y;
            sA[(c4 * 4 + 2) * 64 + mm] = v.z;
            sA[(c4 * 4 + 3) * 64 + mm] = v.w;
        }
#pragma unroll
        for (int j = 0; j < 2; j++) {
            int f = tid + j * 256;            // 0..511 float4 units
            int rr = f >> 4, c4 = f & 15;
            reinterpret_cast<float4*>(sB)[f] =
                reinterpret_cast<const float4*>(g_value)[(kt + rr) * 32 + (bn >> 2) + c4];
        }
        __syncthreads();
#pragma unroll
        for (int kk = 0; kk < 32; kk++) {
            float4 a4 = *reinterpret_cast<const float4*>(&sA[kk * 64 + ty * 4]);
            float4 b4 = *reinterpret_cast<const float4*>(&sB[kk * 64 + tx * 4]);
            float a[4] = {a4.x, a4.y, a4.z, a4.w};
            float bvv[4] = {b4.x, b4.y, b4.z, b4.w};
#pragma unroll
            for (int i = 0; i < 4; i++)
#pragma unroll
                for (int j = 0; j < 4; j++)
                    acc[i][j] = fmaf(a[i], bvv[j], acc[i][j]);
        }
    }

    if (kz == 0) {
        // epilogue: + we[bm:bm+64, 0:32] @ Wfe[0:32, bn:bn+64]
        __syncthreads();
#pragma unroll
        for (int j = 0; j < 2; j++) {
            int f = tid + j * 256;
            int mm = f >> 3, c4 = f & 7;
            float4 v = reinterpret_cast<const float4*>(g_we)[(bm + mm) * 8 + c4];
            sA[(c4 * 4 + 0) * 64 + mm] = v.x;
            sA[(c4 * 4 + 1) * 64 + mm] = v.y;
            sA[(c4 * 4 + 2) * 64 + mm] = v.z;
            sA[(c4 * 4 + 3) * 64 + mm] = v.w;
        }
#pragma unroll
        for (int j = 0; j < 2; j++) {
            int f = tid + j * 256;
            int rr = f >> 4, c4 = f & 15;
            reinterpret_cast<float4*>(sB)[f] =
                reinterpret_cast<const float4*>(Wfe)[rr * 32 + (bn >> 2) + c4];
        }
        __syncthreads();
#pragma unroll
        for (int kk = 0; kk < 32; kk++) {
            float4 a4 = *reinterpret_cast<const float4*>(&sA[kk * 64 + ty * 4]);
            float4 b4 = *reinterpret_cast<const float4*>(&sB[kk * 64 + tx * 4]);
            float a[4] = {a4.x, a4.y, a4.z, a4.w};
            float bvv[4] = {b4.x, b4.y, b4.z, b4.w};
#pragma unroll
            for (int i = 0; i < 4; i++)
#pragma unroll
                for (int j = 0; j < 4; j++)
                    acc[i][j] = fmaf(a[i], bvv[j], acc[i][j]);
        }
    }
#pragma unroll
    for (int i = 0; i < 4; i++)
#pragma unroll
        for (int j = 0; j < 4; j++)
            g_part[(kz * NN + bm + ty * 4 + i) * ODIM + bn + tx * 4 + j] = acc[i][j];
}

// ============================================================
// out[n, 128:256] = sum_kz part[kz] + bfe
// ============================================================
__global__ void __launch_bounds__(256) reduce_kernel(const float* __restrict__ bfe,
                                                     float* __restrict__ outp) {
    int idx = blockIdx.x * 256 + threadIdx.x;   // 0..131071
    int n = idx >> 7, c = idx & 127;
    float v = bfe[c];
#pragma unroll
    for (int kz = 0; kz < KSPLIT; kz++)
        v += g_part[kz * NN * ODIM + idx];
    outp[n * (2 * ODIM) + ODIM + c] = v;
}

extern "C" void kernel_launch(void* const* d_in, const int* in_sizes, int n_in,
                              void* d_out, int out_size) {
    const float* x     = (const float*)d_in[0];
    const float* neigh = (const float*)d_in[1];
    const float* emb   = (const float*)d_in[2];
    const int*   adj   = (const int*)d_in[3];
    const float* Wx1 = (const float*)d_in[4];  const float* bx1 = (const float*)d_in[5];
    const float* Wx2 = (const float*)d_in[6];  const float* bx2 = (const float*)d_in[7];
    const float* Wn1 = (const float*)d_in[8];  const float* bn1 = (const float*)d_in[9];
    const float* Wn2 = (const float*)d_in[10]; const float* bn2 = (const float*)d_in[11];
    const float* We  = (const float*)d_in[12]; const float* be  = (const float*)d_in[13];
    const float* Wv  = (const float*)d_in[14]; const float* bv  = (const float*)d_in[15];
    const float* Wfe = (const float*)d_in[16]; const float* bfe = (const float*)d_in[17];
    const float* Wfx = (const float*)d_in[18]; const float* bfx = (const float*)d_in[19];
    float* out = (float*)d_out;

    pre_kernel<<<NB_PROJ + 2 * NB_ATT + 2 * NB_GEMM, 256>>>(
        emb, We, be,
        x, Wx1, bx1, Wx2, bx2,
        neigh, Wn1, bn1, Wn2, bn2,
        Wv, bv, Wfx, bfx, out);
    s1_kernel<<<dim3(16, 32), 256>>>();
    row_kernel<<<NN, 256>>>(adj, emb);
    agg_kernel<<<dim3(16, 2, KSPLIT), 256>>>(Wfe);
    reduce_kernel<<<512, 256>>>(bfe, out);
}

// round 6
// speedup vs baseline: 2.2929x; 1.0265x over previous
#include <cuda_runtime.h>
#include <math.h>

#define NN   1024
#define IND  256
#define ED   32
#define HID  32
#define ODIM 128
#define NE   100000

#define NB_PROJ (NE / 32)        // 3125
#define NB_ATT  128              // per att pass (8 rows/block)
#define NB_GEMM 64               // per gemm2 z-slice
#define KSPLIT  16               // agg k-split

// ---- scratch (device globals; no allocation allowed) ----
__device__ float g_proj[NE * ED];        // tanh(edge_emb @ We + be)
__device__ float g_xatt[NN * HID];
__device__ float g_natt[NN * HID];
__device__ float g_value[NN * ODIM];     // neigh @ Wv + bv
__device__ float g_s1[NN * NN];          // x_att @ n_att^T
__device__ float g_ws[NN * NN];          // softmax weights
__device__ float g_we[NN * ED];          // ws-weighted edge embeddings
__device__ float g_part[KSPLIT * NN * ODIM];  // ksplit partials of ws@value

// ============================================================
// device helpers (operate on a shared scratch buffer)
// ============================================================
__device__ __forceinline__ void do_proj(float* sm, int blk,
                                        const float* __restrict__ emb,
                                        const float* __restrict__ We,
                                        const float* __restrict__ be) {
    float* sW = sm;               // 1024
    float* sb = sm + 1024;        // 32
    float* sx = sm + 1024 + 64;   // 1024 (keep 16B alignment)
    int tid = threadIdx.x;
    for (int i = tid; i < 1024; i += 256) sW[i] = We[i];
    if (tid < 32) sb[tid] = be[tid];
    int rows0 = blk * 32;
    reinterpret_cast<float4*>(sx)[tid] =
        reinterpret_cast<const float4*>(emb)[rows0 * 8 + tid];
    __syncthreads();
    int col = tid & 31;
    int r0 = (tid >> 5) * 4;
    float acc0 = sb[col], acc1 = acc0, acc2 = acc0, acc3 = acc0;
#pragma unroll
    for (int d = 0; d < 32; d++) {
        float w = sW[d * 32 + col];
        acc0 = fmaf(sx[(r0 + 0) * 32 + d], w, acc0);
        acc1 = fmaf(sx[(r0 + 1) * 32 + d], w, acc1);
        acc2 = fmaf(sx[(r0 + 2) * 32 + d], w, acc2);
        acc3 = fmaf(sx[(r0 + 3) * 32 + d], w, acc3);
    }
    g_proj[(rows0 + r0 + 0) * 32 + col] = tanhf(acc0);
    g_proj[(rows0 + r0 + 1) * 32 + col] = tanhf(acc1);
    g_proj[(rows0 + r0 + 2) * 32 + col] = tanhf(acc2);
    g_proj[(rows0 + r0 + 3) * 32 + col] = tanhf(acc3);
}

__device__ __forceinline__ void do_att(float* sm, int blk,
                                       const float* __restrict__ X,
                                       const float* __restrict__ W1,
                                       const float* __restrict__ b1,
                                       const float* __restrict__ W2,
                                       const float* __restrict__ b2,
                                       float* __restrict__ dst) {
    float* sx = sm;   // 8 * 256
    int warp = threadIdx.x >> 5, lane = threadIdx.x & 31;
    int row = blk * 8 + warp;
    for (int d = lane; d < IND; d += 32) sx[warp * IND + d] = X[row * IND + d];
    __syncwarp();
    float acc = b1[lane];
#pragma unroll 8
    for (int d = 0; d < IND; d++)
        acc = fmaf(sx[warp * IND + d], W1[d * 32 + lane], acc);
    float h = tanhf(acc);
    float a2 = b2[lane];
#pragma unroll
    for (int j = 0; j < 32; j++)
        a2 = fmaf(__shfl_sync(0xffffffffu, h, j), W2[j * 32 + lane], a2);
    dst[row * 32 + lane] = a2;
}

__device__ __forceinline__ void do_gemm2(float* sm, int blk, int z,
                                         const float* __restrict__ X,
                                         const float* __restrict__ W,
                                         const float* __restrict__ b,
                                         float* __restrict__ outp) {
    float* sX = sm;          // 16 * 256 = 4096
    float* sW = sm + 4096;   // 32 * 128 = 4096
    int tid = threadIdx.x;
    int r0 = blk * 16;
#pragma unroll
    for (int j = 0; j < 4; j++) {
        int f = tid + j * 256;
        int r = f >> 6, c4 = f & 63;
        reinterpret_cast<float4*>(sX)[f] =
            reinterpret_cast<const float4*>(X)[(r0 + r) * 64 + c4];
    }
    int c = tid & 127;
    int rh = tid >> 7;
    float acc[8];
    float bb = b[c];
#pragma unroll
    for (int i = 0; i < 8; i++) acc[i] = bb;

    for (int kt = 0; kt < IND; kt += 32) {
        __syncthreads();
#pragma unroll
        for (int j = 0; j < 4; j++) {
            int f = tid + j * 256;
            int rr = f >> 5, cc = f & 31;
            reinterpret_cast<float4*>(sW)[f] =
                reinterpret_cast<const float4*>(W)[(kt + rr) * 32 + cc];
        }
        __syncthreads();
#pragma unroll
        for (int d = 0; d < 32; d++) {
            float w = sW[d * 128 + c];
#pragma unroll
            for (int i = 0; i < 8; i++)
                acc[i] = fmaf(sX[(rh * 8 + i) * IND + kt + d], w, acc[i]);
        }
    }
    if (z == 0) {
#pragma unroll
        for (int i = 0; i < 8; i++) g_value[(r0 + rh * 8 + i) * ODIM + c] = acc[i];
    } else {
#pragma unroll
        for (int i = 0; i < 8; i++) outp[(r0 + rh * 8 + i) * (2 * ODIM) + c] = acc[i];
    }
}

// ============================================================
// mega-kernel 1: all work independent of each other
// ============================================================
__global__ void __launch_bounds__(256) pre_kernel(
    const float* __restrict__ emb, const float* __restrict__ We,
    const float* __restrict__ be,
    const float* __restrict__ x, const float* __restrict__ Wx1,
    const float* __restrict__ bx1, const float* __restrict__ Wx2,
    const float* __restrict__ bx2,
    const float* __restrict__ neigh, const float* __restrict__ Wn1,
    const float* __restrict__ bn1, const float* __restrict__ Wn2,
    const float* __restrict__ bn2,
    const float* __restrict__ Wv, const float* __restrict__ bv,
    const float* __restrict__ Wfx, const float* __restrict__ bfx,
    float* __restrict__ outp) {
    __shared__ __align__(16) float sm[8192];   // 32 KB, aliased per branch
    int bid = blockIdx.x;
    if (bid < NB_PROJ) {
        do_proj(sm, bid, emb, We, be);
    } else if (bid < NB_PROJ + NB_ATT) {
        do_att(sm, bid - NB_PROJ, x, Wx1, bx1, Wx2, bx2, g_xatt);
    } else if (bid < NB_PROJ + 2 * NB_ATT) {
        do_att(sm, bid - NB_PROJ - NB_ATT, neigh, Wn1, bn1, Wn2, bn2, g_natt);
    } else {
        int local = bid - NB_PROJ - 2 * NB_ATT;
        int z = local >> 6;           // 0..1
        int blk = local & 63;
        if (z == 0) do_gemm2(sm, blk, 0, neigh, Wv, bv, nullptr);
        else        do_gemm2(sm, blk, 1, x, Wfx, bfx, outp);
    }
}

// ============================================================
// S1 = x_att @ n_att^T   (1024 x 1024 x 32)
// 64x32 tiles, 256 threads, 4x2 per thread, grid (16, 32) = 512 blocks
// ============================================================
__global__ void __launch_bounds__(256) s1_kernel() {
    __shared__ __align__(16) float sA[32 * 64];  // [d][m]
    __shared__ __align__(16) float sB[32 * 32];  // [d][k]
    int tid = threadIdx.x;
    int bm = blockIdx.x * 64, bk = blockIdx.y * 32;
#pragma unroll
    for (int j = 0; j < 2; j++) {
        int f = tid + j * 256;          // 0..511 float4 units
        int m = f >> 3, d4 = f & 7;
        float4 va = reinterpret_cast<const float4*>(g_xatt)[(bm + m) * 8 + d4];
        sA[(d4 * 4 + 0) * 64 + m] = va.x;
        sA[(d4 * 4 + 1) * 64 + m] = va.y;
        sA[(d4 * 4 + 2) * 64 + m] = va.z;
        sA[(d4 * 4 + 3) * 64 + m] = va.w;
    }
    {
        int m = tid >> 3, d4 = tid & 7;   // 32 rows x 8 float4
        float4 vb = reinterpret_cast<const float4*>(g_natt)[(bk + m) * 8 + d4];
        sB[(d4 * 4 + 0) * 32 + m] = vb.x;
        sB[(d4 * 4 + 1) * 32 + m] = vb.y;
        sB[(d4 * 4 + 2) * 32 + m] = vb.z;
        sB[(d4 * 4 + 3) * 32 + m] = vb.w;
    }
    __syncthreads();
    int tx = tid & 15, ty = tid >> 4;
    float acc[4][2];
#pragma unroll
    for (int i = 0; i < 4; i++) { acc[i][0] = 0.f; acc[i][1] = 0.f; }
#pragma unroll
    for (int d = 0; d < 32; d++) {
        float4 a4 = *reinterpret_cast<const float4*>(&sA[d * 64 + ty * 4]);
        float b0 = sB[d * 32 + tx * 2];
        float b1 = sB[d * 32 + tx * 2 + 1];
        float a[4] = {a4.x, a4.y, a4.z, a4.w};
#pragma unroll
        for (int i = 0; i < 4; i++) {
            acc[i][0] = fmaf(a[i], b0, acc[i][0]);
            acc[i][1] = fmaf(a[i], b1, acc[i][1]);
        }
    }
#pragma unroll
    for (int i = 0; i < 4; i++) {
        g_s1[(bm + ty * 4 + i) * NN + bk + tx * 2]     = acc[i][0];
        g_s1[(bm + ty * 4 + i) * NN + bk + tx * 2 + 1] = acc[i][1];
    }
}

// ============================================================
// per-row: scores (S1 row + gathered edge term) -> leaky -> mask ->
// softmax -> write ws -> weighted edge-embedding sum
// ============================================================
__global__ void __launch_bounds__(256) row_kernel(const int* __restrict__ adj,
                                                  const float* __restrict__ emb) {
    __shared__ int sadj[NN];
    __shared__ float ss[NN];
    __shared__ __align__(16) float sx[32];
    __shared__ float red[8];
    __shared__ __align__(16) float swe[32 * 32];

    int n = blockIdx.x;
    int tid = threadIdx.x;
    for (int k = tid; k < NN; k += 256) {
        sadj[k] = adj[n * NN + k];
        ss[k] = g_s1[n * NN + k];       // node-node term precomputed
    }
    if (tid < 32) sx[tid] = g_xatt[n * 32 + tid];
    __syncthreads();

    int g = tid >> 3, l8 = tid & 7;
    float4 x4 = reinterpret_cast<const float4*>(sx)[l8];
    const float4* proj4 = reinterpret_cast<const float4*>(g_proj);
    const float4* emb4  = reinterpret_cast<const float4*>(emb);

    // ---- phase 1: scores ----
#pragma unroll 4
    for (int it = 0; it < 32; ++it) {
        int k = it * 32 + g;
        int e = sadj[k];
        float4 p = proj4[e * 8 + l8];   // random 128B row gather (L2)
        float part = fmaf(p.x, x4.x, fmaf(p.y, x4.y, fmaf(p.z, x4.z, p.w * x4.w)));
        part += __shfl_xor_sync(0xffffffffu, part, 1);
        part += __shfl_xor_sync(0xffffffffu, part, 2);
        part += __shfl_xor_sync(0xffffffffu, part, 4);
        if (l8 == 0) {
            float s = ss[k] + part;
            s = s > 0.f ? s : 0.01f * s;             // leaky_relu(0.01)
            ss[k] = (e > 0) ? s : -9e15f;            // mask adj>0
        }
    }
    __syncthreads();

    // ---- phase 2: softmax over k ----
    float m = -3.4e38f;
    for (int k = tid; k < NN; k += 256) m = fmaxf(m, ss[k]);
#pragma unroll
    for (int o = 16; o; o >>= 1) m = fmaxf(m, __shfl_xor_sync(0xffffffffu, m, o));
    if ((tid & 31) == 0) red[tid >> 5] = m;
    __syncthreads();
    if (tid == 0) {
        float t = red[0];
        for (int i = 1; i < 8; i++) t = fmaxf(t, red[i]);
        red[0] = t;
    }
    __syncthreads();
    float M = red[0];
    __syncthreads();

    float Z = 0.f;
    for (int k = tid; k < NN; k += 256) {
        float ev = __expf(ss[k] - M);
        ss[k] = ev;
        Z += ev;
    }
#pragma unroll
    for (int o = 16; o; o >>= 1) Z += __shfl_xor_sync(0xffffffffu, Z, o);
    if ((tid & 31) == 0) red[tid >> 5] = Z;
    __syncthreads();
    if (tid == 0) {
        float t = 0.f;
        for (int i = 0; i < 8; i++) t += red[i];
        red[0] = t;
    }
    __syncthreads();
    float inv = 1.f / red[0];
    for (int k = tid; k < NN; k += 256) {
        float w = ss[k] * inv;
        ss[k] = w;
        g_ws[n * NN + k] = w;
    }
    __syncthreads();

    // ---- phase 3: we[n,:] = sum_k ws[k] * edge_emb[adj[n,k],:] ----
    float4 acc = make_float4(0.f, 0.f, 0.f, 0.f);
#pragma unroll 4
    for (int it = 0; it < 32; ++it) {
        int k = it * 32 + g;
        float w = ss[k];
        int e = sadj[k];
        float4 em = emb4[e * 8 + l8];   // second random gather (L2)
        acc.x += w * em.x; acc.y += w * em.y;
        acc.z += w * em.z; acc.w += w * em.w;
    }
    reinterpret_cast<float4*>(swe)[g * 8 + l8] = acc;
    __syncthreads();
    if (tid < 32) {
        float a = 0.f;
        for (int gg = 0; gg < 32; gg++) a += swe[gg * 32 + tid];
        g_we[n * 32 + tid] = a;
    }
}

// ============================================================
// partials of ws @ value (k-split KSPLIT=16), kz=0 also adds we @ Wfe
// tile: 64 m x 128 n (full N), 4x8 per thread, KCH=64
// grid (16, 16) = 256 blocks
// A staged [m][k] stride 36 (STS.128-friendly, padded), B staged [k][n]
// B read as two float4s at n=tx*4 and n=64+tx*4 (conflict-free)
// ============================================================
#define ASTR 36
__global__ void __launch_bounds__(256) agg_kernel(const float* __restrict__ Wfe) {
    __shared__ __align__(16) float sA[64 * ASTR];   // [m][kk], 9216 B
    __shared__ __align__(16) float sB[32 * 128];    // [kk][n], 16384 B
    int tid = threadIdx.x;
    int bm = blockIdx.x * 64;
    int kz = blockIdx.y;
    int tx = tid & 15, ty = tid >> 4;
    int m0 = ty * 4;
    float acc[4][8];
#pragma unroll
    for (int i = 0; i < 4; i++)
#pragma unroll
        for (int j = 0; j < 8; j++) acc[i][j] = 0.f;

    const int KCH = NN / KSPLIT;   // 64
    for (int kt = kz * KCH; kt < kz * KCH + KCH; kt += 32) {
        __syncthreads();
        // stage A = ws[bm:bm+64, kt:kt+32] into [m][k] (stride ASTR)
#pragma unroll
        for (int j = 0; j < 2; j++) {
            int f = tid + j * 256;            // 0..511 float4
            int mm = f >> 3, c4 = f & 7;
            float4 v = reinterpret_cast<const float4*>(g_ws)[(bm + mm) * 256 + (kt >> 2) + c4];
            *reinterpret_cast<float4*>(&sA[mm * ASTR + c4 * 4]) = v;
        }
        // stage B = value[kt:kt+32, 0:128]
#pragma unroll
        for (int j = 0; j < 4; j++) {
            int f = tid + j * 256;            // 0..1023 float4
            reinterpret_cast<float4*>(sB)[f] =
                reinterpret_cast<const float4*>(g_value)[kt * 32 + f];
        }
        __syncthreads();
#pragma unroll
        for (int kk = 0; kk < 32; kk++) {
            float a0 = sA[(m0 + 0) * ASTR + kk];
            float a1 = sA[(m0 + 1) * ASTR + kk];
            float a2 = sA[(m0 + 2) * ASTR + kk];
            float a3 = sA[(m0 + 3) * ASTR + kk];
            float4 bL = *reinterpret_cast<const float4*>(&sB[kk * 128 + tx * 4]);
            float4 bH = *reinterpret_cast<const float4*>(&sB[kk * 128 + 64 + tx * 4]);
            float bb[8] = {bL.x, bL.y, bL.z, bL.w, bH.x, bH.y, bH.z, bH.w};
            float aa[4] = {a0, a1, a2, a3};
#pragma unroll
            for (int i = 0; i < 4; i++)
#pragma unroll
                for (int j = 0; j < 8; j++)
                    acc[i][j] = fmaf(aa[i], bb[j], acc[i][j]);
        }
    }

    if (kz == 0) {
        // epilogue: + we[bm:bm+64, 0:32] @ Wfe[0:32, 0:128]
        __syncthreads();
#pragma unroll
        for (int j = 0; j < 2; j++) {
            int f = tid + j * 256;
            int mm = f >> 3, c4 = f & 7;
            float4 v = reinterpret_cast<const float4*>(g_we)[mm * 8 + c4 + bm * 8];
            *reinterpret_cast<float4*>(&sA[mm * ASTR + c4 * 4]) = v;
        }
#pragma unroll
        for (int j = 0; j < 4; j++) {
            int f = tid + j * 256;
            reinterpret_cast<float4*>(sB)[f] =
                reinterpret_cast<const float4*>(Wfe)[f];
        }
        __syncthreads();
#pragma unroll
        for (int kk = 0; kk < 32; kk++) {
            float a0 = sA[(m0 + 0) * ASTR + kk];
            float a1 = sA[(m0 + 1) * ASTR + kk];
            float a2 = sA[(m0 + 2) * ASTR + kk];
            float a3 = sA[(m0 + 3) * ASTR + kk];
            float4 bL = *reinterpret_cast<const float4*>(&sB[kk * 128 + tx * 4]);
            float4 bH = *reinterpret_cast<const float4*>(&sB[kk * 128 + 64 + tx * 4]);
            float bb[8] = {bL.x, bL.y, bL.z, bL.w, bH.x, bH.y, bH.z, bH.w};
            float aa[4] = {a0, a1, a2, a3};
#pragma unroll
            for (int i = 0; i < 4; i++)
#pragma unroll
                for (int j = 0; j < 8; j++)
                    acc[i][j] = fmaf(aa[i], bb[j], acc[i][j]);
        }
    }

    // write partials: cols tx*4..+3 and 64+tx*4..+3
#pragma unroll
    for (int i = 0; i < 4; i++) {
        float* dst = &g_part[(kz * NN + bm + m0 + i) * ODIM];
        *reinterpret_cast<float4*>(dst + tx * 4) =
            make_float4(acc[i][0], acc[i][1], acc[i][2], acc[i][3]);
        *reinterpret_cast<float4*>(dst + 64 + tx * 4) =
            make_float4(acc[i][4], acc[i][5], acc[i][6], acc[i][7]);
    }
}

// ============================================================
// out[n, 128:256] = sum_kz part[kz] + bfe
// ============================================================
__global__ void __launch_bounds__(256) reduce_kernel(const float* __restrict__ bfe,
                                                     float* __restrict__ outp) {
    int idx = blockIdx.x * 256 + threadIdx.x;   // 0..131071
    int n = idx >> 7, c = idx & 127;
    float v = bfe[c];
#pragma unroll
    for (int kz = 0; kz < KSPLIT; kz++)
        v += g_part[kz * NN * ODIM + idx];
    outp[n * (2 * ODIM) + ODIM + c] = v;
}

extern "C" void kernel_launch(void* const* d_in, const int* in_sizes, int n_in,
                              void* d_out, int out_size) {
    const float* x     = (const float*)d_in[0];
    const float* neigh = (const float*)d_in[1];
    const float* emb   = (const float*)d_in[2];
    const int*   adj   = (const int*)d_in[3];
    const float* Wx1 = (const float*)d_in[4];  const float* bx1 = (const float*)d_in[5];
    const float* Wx2 = (const float*)d_in[6];  const float* bx2 = (const float*)d_in[7];
    const float* Wn1 = (const float*)d_in[8];  const float* bn1 = (const float*)d_in[9];
    const float* Wn2 = (const float*)d_in[10]; const float* bn2 = (const float*)d_in[11];
    const float* We  = (const float*)d_in[12]; const float* be  = (const float*)d_in[13];
    const float* Wv  = (const float*)d_in[14]; const float* bv  = (const float*)d_in[15];
    const float* Wfe = (const float*)d_in[16]; const float* bfe = (const float*)d_in[17];
    const float* Wfx = (const float*)d_in[18]; const float* bfx = (const float*)d_in[19];
    float* out = (float*)d_out;

    pre_kernel<<<NB_PROJ + 2 * NB_ATT + 2 * NB_GEMM, 256>>>(
        emb, We, be,
        x, Wx1, bx1, Wx2, bx2,
        neigh, Wn1, bn1, Wn2, bn2,
        Wv, bv, Wfx, bfx, out);
    s1_kernel<<<dim3(16, 32), 256>>>();
    row_kernel<<<NN, 256>>>(adj, emb);
    agg_kernel<<<dim3(16, KSPLIT), 256>>>(Wfe);
    reduce_kernel<<<512, 256>>>(bfe, out);
}

// round 7
// speedup vs baseline: 2.2938x; 1.0004x over previous
#include <cuda_runtime.h>
#include <math.h>

#define NN   1024
#define IND  256
#define ED   32
#define HID  32
#define ODIM 128
#define NE   100000

#define NB_PROJ (NE / 32)        // 3125
#define NB_ATT  128              // per att pass (8 rows/block)
#define NB_GEMM 64               // per gemm2 z-slice
#define KSPLIT  32               // agg k-split

// ---- scratch (device globals; no allocation allowed) ----
__device__ float g_proj[NE * ED];        // tanh(edge_emb @ We + be)
__device__ float g_xatt[NN * HID];
__device__ float g_natt[NN * HID];
__device__ float g_value[NN * ODIM];     // neigh @ Wv + bv
__device__ float g_s1[NN * NN];          // x_att @ n_att^T
__device__ float g_ws[NN * NN];          // softmax weights
__device__ float g_we[NN * ED];          // ws-weighted edge embeddings
__device__ float g_part[KSPLIT * NN * ODIM];  // ksplit partials of ws@value

// ============================================================
// device helpers (operate on a shared scratch buffer)
// ============================================================
__device__ __forceinline__ void do_proj(float* sm, int blk,
                                        const float* __restrict__ emb,
                                        const float* __restrict__ We,
                                        const float* __restrict__ be) {
    float* sW = sm;               // 1024
    float* sb = sm + 1024;        // 32
    float* sx = sm + 1024 + 64;   // 1024 (keep 16B alignment)
    int tid = threadIdx.x;
    for (int i = tid; i < 1024; i += 256) sW[i] = We[i];
    if (tid < 32) sb[tid] = be[tid];
    int rows0 = blk * 32;
    reinterpret_cast<float4*>(sx)[tid] =
        reinterpret_cast<const float4*>(emb)[rows0 * 8 + tid];
    __syncthreads();
    int col = tid & 31;
    int r0 = (tid >> 5) * 4;
    float acc0 = sb[col], acc1 = acc0, acc2 = acc0, acc3 = acc0;
#pragma unroll
    for (int d = 0; d < 32; d++) {
        float w = sW[d * 32 + col];
        acc0 = fmaf(sx[(r0 + 0) * 32 + d], w, acc0);
        acc1 = fmaf(sx[(r0 + 1) * 32 + d], w, acc1);
        acc2 = fmaf(sx[(r0 + 2) * 32 + d], w, acc2);
        acc3 = fmaf(sx[(r0 + 3) * 32 + d], w, acc3);
    }
    g_proj[(rows0 + r0 + 0) * 32 + col] = tanhf(acc0);
    g_proj[(rows0 + r0 + 1) * 32 + col] = tanhf(acc1);
    g_proj[(rows0 + r0 + 2) * 32 + col] = tanhf(acc2);
    g_proj[(rows0 + r0 + 3) * 32 + col] = tanhf(acc3);
}

__device__ __forceinline__ void do_att(float* sm, int blk,
                                       const float* __restrict__ X,
                                       const float* __restrict__ W1,
                                       const float* __restrict__ b1,
                                       const float* __restrict__ W2,
                                       const float* __restrict__ b2,
                                       float* __restrict__ dst) {
    float* sx = sm;   // 8 * 256
    int warp = threadIdx.x >> 5, lane = threadIdx.x & 31;
    int row = blk * 8 + warp;
    for (int d = lane; d < IND; d += 32) sx[warp * IND + d] = X[row * IND + d];
    __syncwarp();
    float acc = b1[lane];
#pragma unroll 8
    for (int d = 0; d < IND; d++)
        acc = fmaf(sx[warp * IND + d], W1[d * 32 + lane], acc);
    float h = tanhf(acc);
    float a2 = b2[lane];
#pragma unroll
    for (int j = 0; j < 32; j++)
        a2 = fmaf(__shfl_sync(0xffffffffu, h, j), W2[j * 32 + lane], a2);
    dst[row * 32 + lane] = a2;
}

__device__ __forceinline__ void do_gemm2(float* sm, int blk, int z,
                                         const float* __restrict__ X,
                                         const float* __restrict__ W,
                                         const float* __restrict__ b,
                                         float* __restrict__ outp) {
    float* sX = sm;          // 16 * 256 = 4096
    float* sW = sm + 4096;   // 32 * 128 = 4096
    int tid = threadIdx.x;
    int r0 = blk * 16;
#pragma unroll
    for (int j = 0; j < 4; j++) {
        int f = tid + j * 256;
        int r = f >> 6, c4 = f & 63;
        reinterpret_cast<float4*>(sX)[f] =
            reinterpret_cast<const float4*>(X)[(r0 + r) * 64 + c4];
    }
    int c = tid & 127;
    int rh = tid >> 7;
    float acc[8];
    float bb = b[c];
#pragma unroll
    for (int i = 0; i < 8; i++) acc[i] = bb;

    for (int kt = 0; kt < IND; kt += 32) {
        __syncthreads();
#pragma unroll
        for (int j = 0; j < 4; j++) {
            int f = tid + j * 256;
            int rr = f >> 5, cc = f & 31;
            reinterpret_cast<float4*>(sW)[f] =
                reinterpret_cast<const float4*>(W)[(kt + rr) * 32 + cc];
        }
        __syncthreads();
#pragma unroll
        for (int d = 0; d < 32; d++) {
            float w = sW[d * 128 + c];
#pragma unroll
            for (int i = 0; i < 8; i++)
                acc[i] = fmaf(sX[(rh * 8 + i) * IND + kt + d], w, acc[i]);
        }
    }
    if (z == 0) {
#pragma unroll
        for (int i = 0; i < 8; i++) g_value[(r0 + rh * 8 + i) * ODIM + c] = acc[i];
    } else {
#pragma unroll
        for (int i = 0; i < 8; i++) outp[(r0 + rh * 8 + i) * (2 * ODIM) + c] = acc[i];
    }
}

// ============================================================
// mega-kernel 1: all work independent of each other
// ============================================================
__global__ void __launch_bounds__(256) pre_kernel(
    const float* __restrict__ emb, const float* __restrict__ We,
    const float* __restrict__ be,
    const float* __restrict__ x, const float* __restrict__ Wx1,
    const float* __restrict__ bx1, const float* __restrict__ Wx2,
    const float* __restrict__ bx2,
    const float* __restrict__ neigh, const float* __restrict__ Wn1,
    const float* __restrict__ bn1, const float* __restrict__ Wn2,
    const float* __restrict__ bn2,
    const float* __restrict__ Wv, const float* __restrict__ bv,
    const float* __restrict__ Wfx, const float* __restrict__ bfx,
    float* __restrict__ outp) {
    __shared__ __align__(16) float sm[8192];   // 32 KB, aliased per branch
    int bid = blockIdx.x;
    if (bid < NB_PROJ) {
        do_proj(sm, bid, emb, We, be);
    } else if (bid < NB_PROJ + NB_ATT) {
        do_att(sm, bid - NB_PROJ, x, Wx1, bx1, Wx2, bx2, g_xatt);
    } else if (bid < NB_PROJ + 2 * NB_ATT) {
        do_att(sm, bid - NB_PROJ - NB_ATT, neigh, Wn1, bn1, Wn2, bn2, g_natt);
    } else {
        int local = bid - NB_PROJ - 2 * NB_ATT;
        int z = local >> 6;           // 0..1
        int blk = local & 63;
        if (z == 0) do_gemm2(sm, blk, 0, neigh, Wv, bv, nullptr);
        else        do_gemm2(sm, blk, 1, x, Wfx, bfx, outp);
    }
}

// ============================================================
// S1 = x_att @ n_att^T   (1024 x 1024 x 32)
// 64x32 tiles, 256 threads, 4x2 per thread, grid (16, 32) = 512 blocks
// ============================================================
__global__ void __launch_bounds__(256) s1_kernel() {
    __shared__ __align__(16) float sA[32 * 64];  // [d][m]
    __shared__ __align__(16) float sB[32 * 32];  // [d][k]
    int tid = threadIdx.x;
    int bm = blockIdx.x * 64, bk = blockIdx.y * 32;
#pragma unroll
    for (int j = 0; j < 2; j++) {
        int f = tid + j * 256;          // 0..511 float4 units
        int m = f >> 3, d4 = f & 7;
        float4 va = reinterpret_cast<const float4*>(g_xatt)[(bm + m) * 8 + d4];
        sA[(d4 * 4 + 0) * 64 + m] = va.x;
        sA[(d4 * 4 + 1) * 64 + m] = va.y;
        sA[(d4 * 4 + 2) * 64 + m] = va.z;
        sA[(d4 * 4 + 3) * 64 + m] = va.w;
    }
    {
        int m = tid >> 3, d4 = tid & 7;   // 32 rows x 8 float4
        float4 vb = reinterpret_cast<const float4*>(g_natt)[(bk + m) * 8 + d4];
        sB[(d4 * 4 + 0) * 32 + m] = vb.x;
        sB[(d4 * 4 + 1) * 32 + m] = vb.y;
        sB[(d4 * 4 + 2) * 32 + m] = vb.z;
        sB[(d4 * 4 + 3) * 32 + m] = vb.w;
    }
    __syncthreads();
    int tx = tid & 15, ty = tid >> 4;
    float acc[4][2];
#pragma unroll
    for (int i = 0; i < 4; i++) { acc[i][0] = 0.f; acc[i][1] = 0.f; }
#pragma unroll
    for (int d = 0; d < 32; d++) {
        float4 a4 = *reinterpret_cast<const float4*>(&sA[d * 64 + ty * 4]);
        float b0 = sB[d * 32 + tx * 2];
        float b1 = sB[d * 32 + tx * 2 + 1];
        float a[4] = {a4.x, a4.y, a4.z, a4.w};
#pragma unroll
        for (int i = 0; i < 4; i++) {
            acc[i][0] = fmaf(a[i], b0, acc[i][0]);
            acc[i][1] = fmaf(a[i], b1, acc[i][1]);
        }
    }
#pragma unroll
    for (int i = 0; i < 4; i++) {
        g_s1[(bm + ty * 4 + i) * NN + bk + tx * 2]     = acc[i][0];
        g_s1[(bm + ty * 4 + i) * NN + bk + tx * 2 + 1] = acc[i][1];
    }
}

// ============================================================
// per-row: scores (S1 row + gathered edge term) -> leaky -> mask ->
// softmax -> write ws -> weighted edge-embedding sum
// ============================================================
__global__ void __launch_bounds__(256) row_kernel(const int* __restrict__ adj,
                                                  const float* __restrict__ emb) {
    __shared__ int sadj[NN];
    __shared__ float ss[NN];
    __shared__ __align__(16) float sx[32];
    __shared__ float red[8];
    __shared__ __align__(16) float swe[32 * 32];

    int n = blockIdx.x;
    int tid = threadIdx.x;
    for (int k = tid; k < NN; k += 256) {
        sadj[k] = adj[n * NN + k];
        ss[k] = g_s1[n * NN + k];       // node-node term precomputed
    }
    if (tid < 32) sx[tid] = g_xatt[n * 32 + tid];
    __syncthreads();

    int g = tid >> 3, l8 = tid & 7;
    float4 x4 = reinterpret_cast<const float4*>(sx)[l8];
    const float4* proj4 = reinterpret_cast<const float4*>(g_proj);
    const float4* emb4  = reinterpret_cast<const float4*>(emb);

    // ---- phase 1: scores ----
#pragma unroll 4
    for (int it = 0; it < 32; ++it) {
        int k = it * 32 + g;
        int e = sadj[k];
        float4 p = proj4[e * 8 + l8];   // random 128B row gather (L2)
        float part = fmaf(p.x, x4.x, fmaf(p.y, x4.y, fmaf(p.z, x4.z, p.w * x4.w)));
        part += __shfl_xor_sync(0xffffffffu, part, 1);
        part += __shfl_xor_sync(0xffffffffu, part, 2);
        part += __shfl_xor_sync(0xffffffffu, part, 4);
        if (l8 == 0) {
            float s = ss[k] + part;
            s = s > 0.f ? s : 0.01f * s;             // leaky_relu(0.01)
            ss[k] = (e > 0) ? s : -9e15f;            // mask adj>0
        }
    }
    __syncthreads();

    // ---- phase 2: softmax over k ----
    float m = -3.4e38f;
    for (int k = tid; k < NN; k += 256) m = fmaxf(m, ss[k]);
#pragma unroll
    for (int o = 16; o; o >>= 1) m = fmaxf(m, __shfl_xor_sync(0xffffffffu, m, o));
    if ((tid & 31) == 0) red[tid >> 5] = m;
    __syncthreads();
    if (tid == 0) {
        float t = red[0];
        for (int i = 1; i < 8; i++) t = fmaxf(t, red[i]);
        red[0] = t;
    }
    __syncthreads();
    float M = red[0];
    __syncthreads();

    float Z = 0.f;
    for (int k = tid; k < NN; k += 256) {
        float ev = __expf(ss[k] - M);
        ss[k] = ev;
        Z += ev;
    }
#pragma unroll
    for (int o = 16; o; o >>= 1) Z += __shfl_xor_sync(0xffffffffu, Z, o);
    if ((tid & 31) == 0) red[tid >> 5] = Z;
    __syncthreads();
    if (tid == 0) {
        float t = 0.f;
        for (int i = 0; i < 8; i++) t += red[i];
        red[0] = t;
    }
    __syncthreads();
    float inv = 1.f / red[0];
    for (int k = tid; k < NN; k += 256) {
        float w = ss[k] * inv;
        ss[k] = w;
        g_ws[n * NN + k] = w;
    }
    __syncthreads();

    // ---- phase 3: we[n,:] = sum_k ws[k] * edge_emb[adj[n,k],:] ----
    float4 acc = make_float4(0.f, 0.f, 0.f, 0.f);
#pragma unroll 4
    for (int it = 0; it < 32; ++it) {
        int k = it * 32 + g;
        float w = ss[k];
        int e = sadj[k];
        float4 em = emb4[e * 8 + l8];   // second random gather (L2)
        acc.x += w * em.x; acc.y += w * em.y;
        acc.z += w * em.z; acc.w += w * em.w;
    }
    reinterpret_cast<float4*>(swe)[g * 8 + l8] = acc;
    __syncthreads();
    if (tid < 32) {
        float a = 0.f;
        for (int gg = 0; gg < 32; gg++) a += swe[gg * 32 + tid];
        g_we[n * 32 + tid] = a;
    }
}

// ============================================================
// partials of ws @ value (k-split KSPLIT=32), kz=0 also adds we @ Wfe
// tile: 64 m x 128 n (full N), 4x8 per thread, KCH=32
// grid (16, 32) = 512 blocks
// ============================================================
#define ASTR 36
__global__ void __launch_bounds__(256) agg_kernel(const float* __restrict__ Wfe) {
    __shared__ __align__(16) float sA[64 * ASTR];   // [m][kk]
    __shared__ __align__(16) float sB[32 * 128];    // [kk][n]
    int tid = threadIdx.x;
    int bm = blockIdx.x * 64;
    int kz = blockIdx.y;
    int tx = tid & 15, ty = tid >> 4;
    int m0 = ty * 4;
    float acc[4][8];
#pragma unroll
    for (int i = 0; i < 4; i++)
#pragma unroll
        for (int j = 0; j < 8; j++) acc[i][j] = 0.f;

    const int KCH = NN / KSPLIT;   // 32
    {
        int kt = kz * KCH;
        // stage A = ws[bm:bm+64, kt:kt+32] into [m][k] (stride ASTR)
#pragma unroll
        for (int j = 0; j < 2; j++) {
            int f = tid + j * 256;            // 0..511 float4
            int mm = f >> 3, c4 = f & 7;
            float4 v = reinterpret_cast<const float4*>(g_ws)[(bm + mm) * 256 + (kt >> 2) + c4];
            *reinterpret_cast<float4*>(&sA[mm * ASTR + c4 * 4]) = v;
        }
        // stage B = value[kt:kt+32, 0:128]
#pragma unroll
        for (int j = 0; j < 4; j++) {
            int f = tid + j * 256;            // 0..1023 float4
            reinterpret_cast<float4*>(sB)[f] =
                reinterpret_cast<const float4*>(g_value)[kt * 32 + f];
        }
        __syncthreads();
#pragma unroll
        for (int kk = 0; kk < 32; kk++) {
            float a0 = sA[(m0 + 0) * ASTR + kk];
            float a1 = sA[(m0 + 1) * ASTR + kk];
            float a2 = sA[(m0 + 2) * ASTR + kk];
            float a3 = sA[(m0 + 3) * ASTR + kk];
            float4 bL = *reinterpret_cast<const float4*>(&sB[kk * 128 + tx * 4]);
            float4 bH = *reinterpret_cast<const float4*>(&sB[kk * 128 + 64 + tx * 4]);
            float bb[8] = {bL.x, bL.y, bL.z, bL.w, bH.x, bH.y, bH.z, bH.w};
            float aa[4] = {a0, a1, a2, a3};
#pragma unroll
            for (int i = 0; i < 4; i++)
#pragma unroll
                for (int j = 0; j < 8; j++)
                    acc[i][j] = fmaf(aa[i], bb[j], acc[i][j]);
        }
    }

    if (kz == 0) {
        // epilogue: + we[bm:bm+64, 0:32] @ Wfe[0:32, 0:128]
        __syncthreads();
#pragma unroll
        for (int j = 0; j < 2; j++) {
            int f = tid + j * 256;
            int mm = f >> 3, c4 = f & 7;
            float4 v = reinterpret_cast<const float4*>(g_we)[mm * 8 + c4 + bm * 8];
            *reinterpret_cast<float4*>(&sA[mm * ASTR + c4 * 4]) = v;
        }
#pragma unroll
        for (int j = 0; j < 4; j++) {
            int f = tid + j * 256;
            reinterpret_cast<float4*>(sB)[f] =
                reinterpret_cast<const float4*>(Wfe)[f];
        }
        __syncthreads();
#pragma unroll
        for (int kk = 0; kk < 32; kk++) {
            float a0 = sA[(m0 + 0) * ASTR + kk];
            float a1 = sA[(m0 + 1) * ASTR + kk];
            float a2 = sA[(m0 + 2) * ASTR + kk];
            float a3 = sA[(m0 + 3) * ASTR + kk];
            float4 bL = *reinterpret_cast<const float4*>(&sB[kk * 128 + tx * 4]);
            float4 bH = *reinterpret_cast<const float4*>(&sB[kk * 128 + 64 + tx * 4]);
            float bb[8] = {bL.x, bL.y, bL.z, bL.w, bH.x, bH.y, bH.z, bH.w};
            float aa[4] = {a0, a1, a2, a3};
#pragma unroll
            for (int i = 0; i < 4; i++)
#pragma unroll
                for (int j = 0; j < 8; j++)
                    acc[i][j] = fmaf(aa[i], bb[j], acc[i][j]);
        }
    }

    // write partials: cols tx*4..+3 and 64+tx*4..+3
#pragma unroll
    for (int i = 0; i < 4; i++) {
        float* dst = &g_part[(kz * NN + bm + m0 + i) * ODIM];
        *reinterpret_cast<float4*>(dst + tx * 4) =
            make_float4(acc[i][0], acc[i][1], acc[i][2], acc[i][3]);
        *reinterpret_cast<float4*>(dst + 64 + tx * 4) =
            make_float4(acc[i][4], acc[i][5], acc[i][6], acc[i][7]);
    }
}

// ============================================================
// out[n, 128:256] = sum_kz part[kz] + bfe
// ============================================================
__global__ void __launch_bounds__(256) reduce_kernel(const float* __restrict__ bfe,
                                                     float* __restrict__ outp) {
    int idx = blockIdx.x * 256 + threadIdx.x;   // 0..131071
    int n = idx >> 7, c = idx & 127;
    float v = bfe[c];
#pragma unroll
    for (int kz = 0; kz < KSPLIT; kz++)
        v += g_part[kz * NN * ODIM + idx];
    outp[n * (2 * ODIM) + ODIM + c] = v;
}

extern "C" void kernel_launch(void* const* d_in, const int* in_sizes, int n_in,
                              void* d_out, int out_size) {
    const float* x     = (const float*)d_in[0];
    const float* neigh = (const float*)d_in[1];
    const float* emb   = (const float*)d_in[2];
    const int*   adj   = (const int*)d_in[3];
    const float* Wx1 = (const float*)d_in[4];  const float* bx1 = (const float*)d_in[5];
    const float* Wx2 = (const float*)d_in[6];  const float* bx2 = (const float*)d_in[7];
    const float* Wn1 = (const float*)d_in[8];  const float* bn1 = (const float*)d_in[9];
    const float* Wn2 = (const float*)d_in[10]; const float* bn2 = (const float*)d_in[11];
    const float* We  = (const float*)d_in[12]; const float* be  = (const float*)d_in[13];
    const float* Wv  = (const float*)d_in[14]; const float* bv  = (const float*)d_in[15];
    const float* Wfe = (const float*)d_in[16]; const float* bfe = (const float*)d_in[17];
    const float* Wfx = (const float*)d_in[18]; const float* bfx = (const float*)d_in[19];
    float* out = (float*)d_out;

    pre_kernel<<<NB_PROJ + 2 * NB_ATT + 2 * NB_GEMM, 256>>>(
        emb, We, be,
        x, Wx1, bx1, Wx2, bx2,
        neigh, Wn1, bn1, Wn2, bn2,
        Wv, bv, Wfx, bfx, out);
    s1_kernel<<<dim3(16, 32), 256>>>();
    row_kernel<<<NN, 256>>>(adj, emb);
    agg_kernel<<<dim3(16, KSPLIT), 256>>>(Wfe);
    reduce_kernel<<<512, 256>>>(bfe, out);
}

// round 8
// speedup vs baseline: 2.3252x; 1.0137x over previous
#include <cuda_runtime.h>
#include <cuda_fp16.h>
#include <math.h>

#define NN   1024
#define IND  256
#define ED   32
#define HID  32
#define ODIM 128
#define NE   100000

#define NB_PROJ (NE / 32)        // 3125
#define NB_CVT  1563             // emb fp32 -> fp16 (2048 elems/block)
#define NB_ATT  128              // per att pass (8 rows/block)
#define NB_GEMM 64               // per gemm2 z-slice
#define KSPLIT  32               // agg k-split

// ---- scratch (device globals; no allocation allowed) ----
__device__ __half g_projh[NE * ED];      // fp16 tanh(edge_emb @ We + be)
__device__ __half g_embh[NE * ED];       // fp16 copy of edge_emb
__device__ float g_xatt[NN * HID];
__device__ float g_natt[NN * HID];
__device__ float g_value[NN * ODIM];     // neigh @ Wv + bv
__device__ float g_s1[NN * NN];          // x_att @ n_att^T
__device__ float g_ws[NN * NN];          // softmax weights
__device__ float g_we[NN * ED];          // ws-weighted edge embeddings
__device__ float g_part[KSPLIT * NN * ODIM];  // ksplit partials of ws@value

// ============================================================
// device helpers (operate on a shared scratch buffer)
// ============================================================
__device__ __forceinline__ void do_proj(float* sm, int blk,
                                        const float* __restrict__ emb,
                                        const float* __restrict__ We,
                                        const float* __restrict__ be) {
    float* sW = sm;               // 1024
    float* sb = sm + 1024;        // 32
    float* sx = sm + 1024 + 64;   // 1024 (keep 16B alignment)
    int tid = threadIdx.x;
    for (int i = tid; i < 1024; i += 256) sW[i] = We[i];
    if (tid < 32) sb[tid] = be[tid];
    int rows0 = blk * 32;
    reinterpret_cast<float4*>(sx)[tid] =
        reinterpret_cast<const float4*>(emb)[rows0 * 8 + tid];
    __syncthreads();
    int col = tid & 31;
    int r0 = (tid >> 5) * 4;
    float acc0 = sb[col], acc1 = acc0, acc2 = acc0, acc3 = acc0;
#pragma unroll
    for (int d = 0; d < 32; d++) {
        float w = sW[d * 32 + col];
        acc0 = fmaf(sx[(r0 + 0) * 32 + d], w, acc0);
        acc1 = fmaf(sx[(r0 + 1) * 32 + d], w, acc1);
        acc2 = fmaf(sx[(r0 + 2) * 32 + d], w, acc2);
        acc3 = fmaf(sx[(r0 + 3) * 32 + d], w, acc3);
    }
    g_projh[(rows0 + r0 + 0) * 32 + col] = __float2half(tanhf(acc0));
    g_projh[(rows0 + r0 + 1) * 32 + col] = __float2half(tanhf(acc1));
    g_projh[(rows0 + r0 + 2) * 32 + col] = __float2half(tanhf(acc2));
    g_projh[(rows0 + r0 + 3) * 32 + col] = __float2half(tanhf(acc3));
}

__device__ __forceinline__ void do_cvt(int blk, const float* __restrict__ emb) {
    int base = blk * 2048 + threadIdx.x * 8;
    if (base >= NE * ED) return;
    float4 a = *reinterpret_cast<const float4*>(emb + base);
    float4 b = *reinterpret_cast<const float4*>(emb + base + 4);
    __half2 h[4];
    h[0] = __floats2half2_rn(a.x, a.y);
    h[1] = __floats2half2_rn(a.z, a.w);
    h[2] = __floats2half2_rn(b.x, b.y);
    h[3] = __floats2half2_rn(b.z, b.w);
    *reinterpret_cast<float4*>(&g_embh[base]) = *reinterpret_cast<float4*>(h);
}

__device__ __forceinline__ void do_att(float* sm, int blk,
                                       const float* __restrict__ X,
                                       const float* __restrict__ W1,
                                       const float* __restrict__ b1,
                                       const float* __restrict__ W2,
                                       const float* __restrict__ b2,
                                       float* __restrict__ dst) {
    float* sx = sm;   // 8 * 256
    int warp = threadIdx.x >> 5, lane = threadIdx.x & 31;
    int row = blk * 8 + warp;
    for (int d = lane; d < IND; d += 32) sx[warp * IND + d] = X[row * IND + d];
    __syncwarp();
    float acc = b1[lane];
#pragma unroll 8
    for (int d = 0; d < IND; d++)
        acc = fmaf(sx[warp * IND + d], W1[d * 32 + lane], acc);
    float h = tanhf(acc);
    float a2 = b2[lane];
#pragma unroll
    for (int j = 0; j < 32; j++)
        a2 = fmaf(__shfl_sync(0xffffffffu, h, j), W2[j * 32 + lane], a2);
    dst[row * 32 + lane] = a2;
}

__device__ __forceinline__ void do_gemm2(float* sm, int blk, int z,
                                         const float* __restrict__ X,
                                         const float* __restrict__ W,
                                         const float* __restrict__ b,
                                         float* __restrict__ outp) {
    float* sX = sm;          // 16 * 256 = 4096
    float* sW = sm + 4096;   // 32 * 128 = 4096
    int tid = threadIdx.x;
    int r0 = blk * 16;
#pragma unroll
    for (int j = 0; j < 4; j++) {
        int f = tid + j * 256;
        int r = f >> 6, c4 = f & 63;
        reinterpret_cast<float4*>(sX)[f] =
            reinterpret_cast<const float4*>(X)[(r0 + r) * 64 + c4];
    }
    int c = tid & 127;
    int rh = tid >> 7;
    float acc[8];
    float bb = b[c];
#pragma unroll
    for (int i = 0; i < 8; i++) acc[i] = bb;

    for (int kt = 0; kt < IND; kt += 32) {
        __syncthreads();
#pragma unroll
        for (int j = 0; j < 4; j++) {
            int f = tid + j * 256;
            int rr = f >> 5, cc = f & 31;
            reinterpret_cast<float4*>(sW)[f] =
                reinterpret_cast<const float4*>(W)[(kt + rr) * 32 + cc];
        }
        __syncthreads();
#pragma unroll
        for (int d = 0; d < 32; d++) {
            float w = sW[d * 128 + c];
#pragma unroll
            for (int i = 0; i < 8; i++)
                acc[i] = fmaf(sX[(rh * 8 + i) * IND + kt + d], w, acc[i]);
        }
    }
    if (z == 0) {
#pragma unroll
        for (int i = 0; i < 8; i++) g_value[(r0 + rh * 8 + i) * ODIM + c] = acc[i];
    } else {
#pragma unroll
        for (int i = 0; i < 8; i++) outp[(r0 + rh * 8 + i) * (2 * ODIM) + c] = acc[i];
    }
}

// ============================================================
// mega-kernel 1: all independent front-end work
// ============================================================
__global__ void __launch_bounds__(256) pre_kernel(
    const float* __restrict__ emb, const float* __restrict__ We,
    const float* __restrict__ be,
    const float* __restrict__ x, const float* __restrict__ Wx1,
    const float* __restrict__ bx1, const float* __restrict__ Wx2,
    const float* __restrict__ bx2,
    const float* __restrict__ neigh, const float* __restrict__ Wn1,
    const float* __restrict__ bn1, const float* __restrict__ Wn2,
    const float* __restrict__ bn2,
    const float* __restrict__ Wv, const float* __restrict__ bv,
    const float* __restrict__ Wfx, const float* __restrict__ bfx,
    float* __restrict__ outp) {
    __shared__ __align__(16) float sm[8192];   // 32 KB, aliased per branch
    int bid = blockIdx.x;
    if (bid < NB_PROJ) {
        do_proj(sm, bid, emb, We, be);
    } else if (bid < NB_PROJ + NB_CVT) {
        do_cvt(bid - NB_PROJ, emb);
    } else if (bid < NB_PROJ + NB_CVT + NB_ATT) {
        do_att(sm, bid - NB_PROJ - NB_CVT, x, Wx1, bx1, Wx2, bx2, g_xatt);
    } else if (bid < NB_PROJ + NB_CVT + 2 * NB_ATT) {
        do_att(sm, bid - NB_PROJ - NB_CVT - NB_ATT, neigh, Wn1, bn1, Wn2, bn2, g_natt);
    } else {
        int local = bid - NB_PROJ - NB_CVT - 2 * NB_ATT;
        int z = local >> 6;           // 0..1
        int blk = local & 63;
        if (z == 0) do_gemm2(sm, blk, 0, neigh, Wv, bv, nullptr);
        else        do_gemm2(sm, blk, 1, x, Wfx, bfx, outp);
    }
}

// ============================================================
// S1 = x_att @ n_att^T   (1024 x 1024 x 32)
// 64x32 tiles, 256 threads, 4x2 per thread, grid (16, 32) = 512 blocks
// ============================================================
__global__ void __launch_bounds__(256) s1_kernel() {
    __shared__ __align__(16) float sA[32 * 64];  // [d][m]
    __shared__ __align__(16) float sB[32 * 32];  // [d][k]
    int tid = threadIdx.x;
    int bm = blockIdx.x * 64, bk = blockIdx.y * 32;
#pragma unroll
    for (int j = 0; j < 2; j++) {
        int f = tid + j * 256;          // 0..511 float4 units
        int m = f >> 3, d4 = f & 7;
        float4 va = reinterpret_cast<const float4*>(g_xatt)[(bm + m) * 8 + d4];
        sA[(d4 * 4 + 0) * 64 + m] = va.x;
        sA[(d4 * 4 + 1) * 64 + m] = va.y;
        sA[(d4 * 4 + 2) * 64 + m] = va.z;
        sA[(d4 * 4 + 3) * 64 + m] = va.w;
    }
    {
        int m = tid >> 3, d4 = tid & 7;   // 32 rows x 8 float4
        float4 vb = reinterpret_cast<const float4*>(g_natt)[(bk + m) * 8 + d4];
        sB[(d4 * 4 + 0) * 32 + m] = vb.x;
        sB[(d4 * 4 + 1) * 32 + m] = vb.y;
        sB[(d4 * 4 + 2) * 32 + m] = vb.z;
        sB[(d4 * 4 + 3) * 32 + m] = vb.w;
    }
    __syncthreads();
    int tx = tid & 15, ty = tid >> 4;
    float acc[4][2];
#pragma unroll
    for (int i = 0; i < 4; i++) { acc[i][0] = 0.f; acc[i][1] = 0.f; }
#pragma unroll
    for (int d = 0; d < 32; d++) {
        float4 a4 = *reinterpret_cast<const float4*>(&sA[d * 64 + ty * 4]);
        float b0 = sB[d * 32 + tx * 2];
        float b1 = sB[d * 32 + tx * 2 + 1];
        float a[4] = {a4.x, a4.y, a4.z, a4.w};
#pragma unroll
        for (int i = 0; i < 4; i++) {
            acc[i][0] = fmaf(a[i], b0, acc[i][0]);
            acc[i][1] = fmaf(a[i], b1, acc[i][1]);
        }
    }
#pragma unroll
    for (int i = 0; i < 4; i++) {
        g_s1[(bm + ty * 4 + i) * NN + bk + tx * 2]     = acc[i][0];
        g_s1[(bm + ty * 4 + i) * NN + bk + tx * 2 + 1] = acc[i][1];
    }
}

// ============================================================
// per-row: scores (S1 row + fp16 gathered edge term) -> leaky -> mask ->
// softmax -> write ws -> fp16 weighted edge-embedding sum
// 64 groups of 4 lanes; each lane loads float4 = 8 halfs of a row
// ============================================================
__global__ void __launch_bounds__(256) row_kernel(const int* __restrict__ adj) {
    __shared__ int sadj[NN];
    __shared__ float ss[NN];
    __shared__ __align__(16) float sx[32];
    __shared__ float red[8];
    __shared__ __align__(16) float swe[64 * 33];

    int n = blockIdx.x;
    int tid = threadIdx.x;
    for (int k = tid; k < NN; k += 256) {
        sadj[k] = adj[n * NN + k];
        ss[k] = g_s1[n * NN + k];       // node-node term precomputed
    }
    if (tid < 32) sx[tid] = g_xatt[n * 32 + tid];
    __syncthreads();

    int g = tid >> 2, l4 = tid & 3;      // 64 groups of 4 lanes
    float xr[8];
#pragma unroll
    for (int j = 0; j < 8; j++) xr[j] = sx[l4 * 8 + j];

    const float4* proj4 = reinterpret_cast<const float4*>(g_projh);  // 4 per row
    const float4* emb4  = reinterpret_cast<const float4*>(g_embh);   // 4 per row

    // ---- phase 1: scores (fp16 proj gather, 64B/row) ----
#pragma unroll 4
    for (int it = 0; it < 16; ++it) {
        int k = it * 64 + g;
        int e = sadj[k];
        float4 p4 = proj4[e * 4 + l4];
        const __half2* ph = reinterpret_cast<const __half2*>(&p4);
        float part = 0.f;
#pragma unroll
        for (int q = 0; q < 4; q++) {
            float2 f = __half22float2(ph[q]);
            part = fmaf(f.x, xr[2 * q], fmaf(f.y, xr[2 * q + 1], part));
        }
        part += __shfl_xor_sync(0xffffffffu, part, 1);
        part += __shfl_xor_sync(0xffffffffu, part, 2);
        if (l4 == 0) {
            float s = ss[k] + part;
            s = s > 0.f ? s : 0.01f * s;             // leaky_relu(0.01)
            ss[k] = (e > 0) ? s : -9e15f;            // mask adj>0
        }
    }
    __syncthreads();

    // ---- phase 2: softmax over k ----
    float m = -3.4e38f;
    for (int k = tid; k < NN; k += 256) m = fmaxf(m, ss[k]);
#pragma unroll
    for (int o = 16; o; o >>= 1) m = fmaxf(m, __shfl_xor_sync(0xffffffffu, m, o));
    if ((tid & 31) == 0) red[tid >> 5] = m;
    __syncthreads();
    if (tid == 0) {
        float t = red[0];
        for (int i = 1; i < 8; i++) t = fmaxf(t, red[i]);
        red[0] = t;
    }
    __syncthreads();
    float M = red[0];
    __syncthreads();

    float Z = 0.f;
    for (int k = tid; k < NN; k += 256) {
        float ev = __expf(ss[k] - M);
        ss[k] = ev;
        Z += ev;
    }
#pragma unroll
    for (int o = 16; o; o >>= 1) Z += __shfl_xor_sync(0xffffffffu, Z, o);
    if ((tid & 31) == 0) red[tid >> 5] = Z;
    __syncthreads();
    if (tid == 0) {
        float t = 0.f;
        for (int i = 0; i < 8; i++) t += red[i];
        red[0] = t;
    }
    __syncthreads();
    float inv = 1.f / red[0];
    for (int k = tid; k < NN; k += 256) {
        float w = ss[k] * inv;
        ss[k] = w;
        g_ws[n * NN + k] = w;
    }
    __syncthreads();

    // ---- phase 3: we[n,:] = sum_k ws[k] * emb_fp16[adj[n,k],:] ----
    float acc[8];
#pragma unroll
    for (int j = 0; j < 8; j++) acc[j] = 0.f;
#pragma unroll 4
    for (int it = 0; it < 16; ++it) {
        int k = it * 64 + g;
        float w = ss[k];
        int e = sadj[k];
        float4 em4 = emb4[e * 4 + l4];
        const __half2* eh = reinterpret_cast<const __half2*>(&em4);
#pragma unroll
        for (int q = 0; q < 4; q++) {
            float2 f = __half22float2(eh[q]);
            acc[2 * q]     = fmaf(w, f.x, acc[2 * q]);
            acc[2 * q + 1] = fmaf(w, f.y, acc[2 * q + 1]);
        }
    }
#pragma unroll
    for (int j = 0; j < 8; j++) swe[g * 33 + l4 * 8 + j] = acc[j];
    __syncthreads();
    if (tid < 32) {
        float a = 0.f;
#pragma unroll 8
        for (int gg = 0; gg < 64; gg++) a += swe[gg * 33 + tid];
        g_we[n * 32 + tid] = a;
    }
}

// ============================================================
// partials of ws @ value (k-split KSPLIT=32), kz=0 also adds we @ Wfe
// tile: 64 m x 128 n (full N), 4x8 per thread, KCH=32
// grid (16, 32) = 512 blocks
// ============================================================
#define ASTR 36
__global__ void __launch_bounds__(256) agg_kernel(const float* __restrict__ Wfe) {
    __shared__ __align__(16) float sA[64 * ASTR];   // [m][kk]
    __shared__ __align__(16) float sB[32 * 128];    // [kk][n]
    int tid = threadIdx.x;
    int bm = blockIdx.x * 64;
    int kz = blockIdx.y;
    int tx = tid & 15, ty = tid >> 4;
    int m0 = ty * 4;
    float acc[4][8];
#pragma unroll
    for (int i = 0; i < 4; i++)
#pragma unroll
        for (int j = 0; j < 8; j++) acc[i][j] = 0.f;

    const int KCH = NN / KSPLIT;   // 32
    {
        int kt = kz * KCH;
#pragma unroll
        for (int j = 0; j < 2; j++) {
            int f = tid + j * 256;            // 0..511 float4
            int mm = f >> 3, c4 = f & 7;
            float4 v = reinterpret_cast<const float4*>(g_ws)[(bm + mm) * 256 + (kt >> 2) + c4];
            *reinterpret_cast<float4*>(&sA[mm * ASTR + c4 * 4]) = v;
        }
#pragma unroll
        for (int j = 0; j < 4; j++) {
            int f = tid + j * 256;            // 0..1023 float4
            reinterpret_cast<float4*>(sB)[f] =
                reinterpret_cast<const float4*>(g_value)[kt * 32 + f];
        }
        __syncthreads();
#pragma unroll
        for (int kk = 0; kk < 32; kk++) {
            float a0 = sA[(m0 + 0) * ASTR + kk];
            float a1 = sA[(m0 + 1) * ASTR + kk];
            float a2 = sA[(m0 + 2) * ASTR + kk];
            float a3 = sA[(m0 + 3) * ASTR + kk];
            float4 bL = *reinterpret_cast<const float4*>(&sB[kk * 128 + tx * 4]);
            float4 bH = *reinterpret_cast<const float4*>(&sB[kk * 128 + 64 + tx * 4]);
            float bb[8] = {bL.x, bL.y, bL.z, bL.w, bH.x, bH.y, bH.z, bH.w};
            float aa[4] = {a0, a1, a2, a3};
#pragma unroll
            for (int i = 0; i < 4; i++)
#pragma unroll
                for (int j = 0; j < 8; j++)
                    acc[i][j] = fmaf(aa[i], bb[j], acc[i][j]);
        }
    }

    if (kz == 0) {
        // epilogue: + we[bm:bm+64, 0:32] @ Wfe[0:32, 0:128]
        __syncthreads();
#pragma unroll
        for (int j = 0; j < 2; j++) {
            int f = tid + j * 256;
            int mm = f >> 3, c4 = f & 7;
            float4 v = reinterpret_cast<const float4*>(g_we)[mm * 8 + c4 + bm * 8];
            *reinterpret_cast<float4*>(&sA[mm * ASTR + c4 * 4]) = v;
        }
#pragma unroll
        for (int j = 0; j < 4; j++) {
            int f = tid + j * 256;
            reinterpret_cast<float4*>(sB)[f] =
                reinterpret_cast<const float4*>(Wfe)[f];
        }
        __syncthreads();
#pragma unroll
        for (int kk = 0; kk < 32; kk++) {
            float a0 = sA[(m0 + 0) * ASTR + kk];
            float a1 = sA[(m0 + 1) * ASTR + kk];
            float a2 = sA[(m0 + 2) * ASTR + kk];
            float a3 = sA[(m0 + 3) * ASTR + kk];
            float4 bL = *reinterpret_cast<const float4*>(&sB[kk * 128 + tx * 4]);
            float4 bH = *reinterpret_cast<const float4*>(&sB[kk * 128 + 64 + tx * 4]);
            float bb[8] = {bL.x, bL.y, bL.z, bL.w, bH.x, bH.y, bH.z, bH.w};
            float aa[4] = {a0, a1, a2, a3};
#pragma unroll
            for (int i = 0; i < 4; i++)
#pragma unroll
                for (int j = 0; j < 8; j++)
                    acc[i][j] = fmaf(aa[i], bb[j], acc[i][j]);
        }
    }

#pragma unroll
    for (int i = 0; i < 4; i++) {
        float* dst = &g_part[(kz * NN + bm + m0 + i) * ODIM];
        *reinterpret_cast<float4*>(dst + tx * 4) =
            make_float4(acc[i][0], acc[i][1], acc[i][2], acc[i][3]);
        *reinterpret_cast<float4*>(dst + 64 + tx * 4) =
            make_float4(acc[i][4], acc[i][5], acc[i][6], acc[i][7]);
    }
}

// ============================================================
// out[n, 128:256] = sum_kz part[kz] + bfe
// ============================================================
__global__ void __launch_bounds__(256) reduce_kernel(const float* __restrict__ bfe,
                                                     float* __restrict__ outp) {
    int idx = blockIdx.x * 256 + threadIdx.x;   // 0..131071
    int n = idx >> 7, c = idx & 127;
    float v = bfe[c];
#pragma unroll
    for (int kz = 0; kz < KSPLIT; kz++)
        v += g_part[kz * NN * ODIM + idx];
    outp[n * (2 * ODIM) + ODIM + c] = v;
}

extern "C" void kernel_launch(void* const* d_in, const int* in_sizes, int n_in,
                              void* d_out, int out_size) {
    const float* x     = (const float*)d_in[0];
    const float* neigh = (const float*)d_in[1];
    const float* emb   = (const float*)d_in[2];
    const int*   adj   = (const int*)d_in[3];
    const float* Wx1 = (const float*)d_in[4];  const float* bx1 = (const float*)d_in[5];
    const float* Wx2 = (const float*)d_in[6];  const float* bx2 = (const float*)d_in[7];
    const float* Wn1 = (const float*)d_in[8];  const float* bn1 = (const float*)d_in[9];
    const float* Wn2 = (const float*)d_in[10]; const float* bn2 = (const float*)d_in[11];
    const float* We  = (const float*)d_in[12]; const float* be  = (const float*)d_in[13];
    const float* Wv  = (const float*)d_in[14]; const float* bv  = (const float*)d_in[15];
    const float* Wfe = (const float*)d_in[16]; const float* bfe = (const float*)d_in[17];
    const float* Wfx = (const float*)d_in[18]; const float* bfx = (const float*)d_in[19];
    float* out = (float*)d_out;

    pre_kernel<<<NB_PROJ + NB_CVT + 2 * NB_ATT + 2 * NB_GEMM, 256>>>(
        emb, We, be,
        x, Wx1, bx1, Wx2, bx2,
        neigh, Wn1, bn1, Wn2, bn2,
        Wv, bv, Wfx, bfx, out);
    s1_kernel<<<dim3(16, 32), 256>>>();
    row_kernel<<<NN, 256>>>(adj);
    agg_kernel<<<dim3(16, KSPLIT), 256>>>(Wfe);
    reduce_kernel<<<512, 256>>>(bfe, out);
}

// round 9
// speedup vs baseline: 2.3605x; 1.0152x over previous
#include <cuda_runtime.h>
#include <cuda_fp16.h>
#include <math.h>

#define NN   1024
#define IND  256
#define ED   32
#define HID  32
#define ODIM 128
#define NE   100000

#define NB_PROJ (NE / 32)        // 3125
#define NB_CVT  1563             // emb fp32 -> fp16 (2048 elems/block)
#define NB_ATT  128              // per att pass (8 rows/block)
#define NB_GEMM 64               // per gemm2 z-slice
#define KSPLIT  32               // agg k-split

// ---- scratch (device globals; no allocation allowed) ----
__device__ __half g_projh[NE * ED];      // fp16 tanh(edge_emb @ We + be)
__device__ __half g_embh[NE * ED];       // fp16 copy of edge_emb
__device__ float g_xatt[NN * HID];
__device__ float g_natt[NN * HID];
__device__ float g_value[NN * ODIM];     // neigh @ Wv + bv
__device__ float g_s1[NN * NN];          // x_att @ n_att^T
__device__ float g_ws[NN * NN];          // softmax weights
__device__ float g_we[NN * ED];          // ws-weighted edge embeddings
__device__ float g_part[KSPLIT * NN * ODIM];  // ksplit partials of ws@value

// single-instruction MUFU tanh (sm_75+), ~2^-11 max error
__device__ __forceinline__ float fast_tanh(float x) {
    float y;
    asm("tanh.approx.f32 %0, %1;" : "=f"(y) : "f"(x));
    return y;
}

// ============================================================
// device helpers (operate on a shared scratch buffer)
// ============================================================
__device__ __forceinline__ void do_proj(float* sm, int blk,
                                        const float* __restrict__ emb,
                                        const float* __restrict__ We,
                                        const float* __restrict__ be) {
    float* sW = sm;               // 1024
    float* sb = sm + 1024;        // 32
    float* sx = sm + 1024 + 64;   // 1024 (keep 16B alignment)
    int tid = threadIdx.x;
    for (int i = tid; i < 1024; i += 256) sW[i] = We[i];
    if (tid < 32) sb[tid] = be[tid];
    int rows0 = blk * 32;
    reinterpret_cast<float4*>(sx)[tid] =
        reinterpret_cast<const float4*>(emb)[rows0 * 8 + tid];
    __syncthreads();
    int col = tid & 31;
    int r0 = (tid >> 5) * 4;
    float acc0 = sb[col], acc1 = acc0, acc2 = acc0, acc3 = acc0;
#pragma unroll
    for (int d = 0; d < 32; d++) {
        float w = sW[d * 32 + col];
        acc0 = fmaf(sx[(r0 + 0) * 32 + d], w, acc0);
        acc1 = fmaf(sx[(r0 + 1) * 32 + d], w, acc1);
        acc2 = fmaf(sx[(r0 + 2) * 32 + d], w, acc2);
        acc3 = fmaf(sx[(r0 + 3) * 32 + d], w, acc3);
    }
    g_projh[(rows0 + r0 + 0) * 32 + col] = __float2half(fast_tanh(acc0));
    g_projh[(rows0 + r0 + 1) * 32 + col] = __float2half(fast_tanh(acc1));
    g_projh[(rows0 + r0 + 2) * 32 + col] = __float2half(fast_tanh(acc2));
    g_projh[(rows0 + r0 + 3) * 32 + col] = __float2half(fast_tanh(acc3));
}

__device__ __forceinline__ void do_cvt(int blk, const float* __restrict__ emb) {
    int base = blk * 2048 + threadIdx.x * 8;
    if (base >= NE * ED) return;
    float4 a = *reinterpret_cast<const float4*>(emb + base);
    float4 b = *reinterpret_cast<const float4*>(emb + base + 4);
    __half2 h[4];
    h[0] = __floats2half2_rn(a.x, a.y);
    h[1] = __floats2half2_rn(a.z, a.w);
    h[2] = __floats2half2_rn(b.x, b.y);
    h[3] = __floats2half2_rn(b.z, b.w);
    *reinterpret_cast<float4*>(&g_embh[base]) = *reinterpret_cast<float4*>(h);
}

__device__ __forceinline__ void do_att(float* sm, int blk,
                                       const float* __restrict__ X,
                                       const float* __restrict__ W1,
                                       const float* __restrict__ b1,
                                       const float* __restrict__ W2,
                                       const float* __restrict__ b2,
                                       float* __restrict__ dst) {
    float* sx = sm;   // 8 * 256
    int warp = threadIdx.x >> 5, lane = threadIdx.x & 31;
    int row = blk * 8 + warp;
    for (int d = lane; d < IND; d += 32) sx[warp * IND + d] = X[row * IND + d];
    __syncwarp();
    float acc = b1[lane];
#pragma unroll 8
    for (int d = 0; d < IND; d++)
        acc = fmaf(sx[warp * IND + d], W1[d * 32 + lane], acc);
    float h = fast_tanh(acc);
    float a2 = b2[lane];
#pragma unroll
    for (int j = 0; j < 32; j++)
        a2 = fmaf(__shfl_sync(0xffffffffu, h, j), W2[j * 32 + lane], a2);
    dst[row * 32 + lane] = a2;
}

__device__ __forceinline__ void do_gemm2(float* sm, int blk, int z,
                                         const float* __restrict__ X,
                                         const float* __restrict__ W,
                                         const float* __restrict__ b,
                                         float* __restrict__ outp) {
    float* sX = sm;          // 16 * 256 = 4096
    float* sW = sm + 4096;   // 32 * 128 = 4096
    int tid = threadIdx.x;
    int r0 = blk * 16;
#pragma unroll
    for (int j = 0; j < 4; j++) {
        int f = tid + j * 256;
        int r = f >> 6, c4 = f & 63;
        reinterpret_cast<float4*>(sX)[f] =
            reinterpret_cast<const float4*>(X)[(r0 + r) * 64 + c4];
    }
    int c = tid & 127;
    int rh = tid >> 7;
    float acc[8];
    float bb = b[c];
#pragma unroll
    for (int i = 0; i < 8; i++) acc[i] = bb;

    for (int kt = 0; kt < IND; kt += 32) {
        __syncthreads();
#pragma unroll
        for (int j = 0; j < 4; j++) {
            int f = tid + j * 256;
            int rr = f >> 5, cc = f & 31;
            reinterpret_cast<float4*>(sW)[f] =
                reinterpret_cast<const float4*>(W)[(kt + rr) * 32 + cc];
        }
        __syncthreads();
#pragma unroll
        for (int d = 0; d < 32; d++) {
            float w = sW[d * 128 + c];
#pragma unroll
            for (int i = 0; i < 8; i++)
                acc[i] = fmaf(sX[(rh * 8 + i) * IND + kt + d], w, acc[i]);
        }
    }
    if (z == 0) {
#pragma unroll
        for (int i = 0; i < 8; i++) g_value[(r0 + rh * 8 + i) * ODIM + c] = acc[i];
    } else {
#pragma unroll
        for (int i = 0; i < 8; i++) outp[(r0 + rh * 8 + i) * (2 * ODIM) + c] = acc[i];
    }
}

// ============================================================
// mega-kernel 1: all independent front-end work
// ============================================================
__global__ void __launch_bounds__(256) pre_kernel(
    const float* __restrict__ emb, const float* __restrict__ We,
    const float* __restrict__ be,
    const float* __restrict__ x, const float* __restrict__ Wx1,
    const float* __restrict__ bx1, const float* __restrict__ Wx2,
    const float* __restrict__ bx2,
    const float* __restrict__ neigh, const float* __restrict__ Wn1,
    const float* __restrict__ bn1, const float* __restrict__ Wn2,
    const float* __restrict__ bn2,
    const float* __restrict__ Wv, const float* __restrict__ bv,
    const float* __restrict__ Wfx, const float* __restrict__ bfx,
    float* __restrict__ outp) {
    __shared__ __align__(16) float sm[8192];   // 32 KB, aliased per branch
    int bid = blockIdx.x;
    if (bid < NB_PROJ) {
        do_proj(sm, bid, emb, We, be);
    } else if (bid < NB_PROJ + NB_CVT) {
        do_cvt(bid - NB_PROJ, emb);
    } else if (bid < NB_PROJ + NB_CVT + NB_ATT) {
        do_att(sm, bid - NB_PROJ - NB_CVT, x, Wx1, bx1, Wx2, bx2, g_xatt);
    } else if (bid < NB_PROJ + NB_CVT + 2 * NB_ATT) {
        do_att(sm, bid - NB_PROJ - NB_CVT - NB_ATT, neigh, Wn1, bn1, Wn2, bn2, g_natt);
    } else {
        int local = bid - NB_PROJ - NB_CVT - 2 * NB_ATT;
        int z = local >> 6;           // 0..1
        int blk = local & 63;
        if (z == 0) do_gemm2(sm, blk, 0, neigh, Wv, bv, nullptr);
        else        do_gemm2(sm, blk, 1, x, Wfx, bfx, outp);
    }
}

// ============================================================
// S1 = x_att @ n_att^T   (1024 x 1024 x 32)
// 64x32 tiles, 256 threads, 4x2 per thread, grid (16, 32) = 512 blocks
// ============================================================
__global__ void __launch_bounds__(256) s1_kernel() {
    __shared__ __align__(16) float sA[32 * 64];  // [d][m]
    __shared__ __align__(16) float sB[32 * 32];  // [d][k]
    int tid = threadIdx.x;
    int bm = blockIdx.x * 64, bk = blockIdx.y * 32;
#pragma unroll
    for (int j = 0; j < 2; j++) {
        int f = tid + j * 256;          // 0..511 float4 units
        int m = f >> 3, d4 = f & 7;
        float4 va = reinterpret_cast<const float4*>(g_xatt)[(bm + m) * 8 + d4];
        sA[(d4 * 4 + 0) * 64 + m] = va.x;
        sA[(d4 * 4 + 1) * 64 + m] = va.y;
        sA[(d4 * 4 + 2) * 64 + m] = va.z;
        sA[(d4 * 4 + 3) * 64 + m] = va.w;
    }
    {
        int m = tid >> 3, d4 = tid & 7;   // 32 rows x 8 float4
        float4 vb = reinterpret_cast<const float4*>(g_natt)[(bk + m) * 8 + d4];
        sB[(d4 * 4 + 0) * 32 + m] = vb.x;
        sB[(d4 * 4 + 1) * 32 + m] = vb.y;
        sB[(d4 * 4 + 2) * 32 + m] = vb.z;
        sB[(d4 * 4 + 3) * 32 + m] = vb.w;
    }
    __syncthreads();
    int tx = tid & 15, ty = tid >> 4;
    float acc[4][2];
#pragma unroll
    for (int i = 0; i < 4; i++) { acc[i][0] = 0.f; acc[i][1] = 0.f; }
#pragma unroll
    for (int d = 0; d < 32; d++) {
        float4 a4 = *reinterpret_cast<const float4*>(&sA[d * 64 + ty * 4]);
        float b0 = sB[d * 32 + tx * 2];
        float b1 = sB[d * 32 + tx * 2 + 1];
        float a[4] = {a4.x, a4.y, a4.z, a4.w};
#pragma unroll
        for (int i = 0; i < 4; i++) {
            acc[i][0] = fmaf(a[i], b0, acc[i][0]);
            acc[i][1] = fmaf(a[i], b1, acc[i][1]);
        }
    }
#pragma unroll
    for (int i = 0; i < 4; i++) {
        g_s1[(bm + ty * 4 + i) * NN + bk + tx * 2]     = acc[i][0];
        g_s1[(bm + ty * 4 + i) * NN + bk + tx * 2 + 1] = acc[i][1];
    }
}

// ============================================================
// per-row: scores (S1 row + fp16 gathered edge term) -> leaky -> mask ->
// softmax -> write ws -> fp16 weighted edge-embedding sum
// 64 groups of 4 lanes; each lane loads float4 = 8 halfs of a row
// ============================================================
__global__ void __launch_bounds__(256) row_kernel(const int* __restrict__ adj) {
    __shared__ int sadj[NN];
    __shared__ float ss[NN];
    __shared__ __align__(16) float sx[32];
    __shared__ float red[8];
    __shared__ __align__(16) float swe[64 * 33];

    int n = blockIdx.x;
    int tid = threadIdx.x;
    for (int k = tid; k < NN; k += 256) {
        sadj[k] = adj[n * NN + k];
        ss[k] = g_s1[n * NN + k];       // node-node term precomputed
    }
    if (tid < 32) sx[tid] = g_xatt[n * 32 + tid];
    __syncthreads();

    int g = tid >> 2, l4 = tid & 3;      // 64 groups of 4 lanes
    float xr[8];
#pragma unroll
    for (int j = 0; j < 8; j++) xr[j] = sx[l4 * 8 + j];

    const float4* proj4 = reinterpret_cast<const float4*>(g_projh);  // 4 per row
    const float4* emb4  = reinterpret_cast<const float4*>(g_embh);   // 4 per row

    // ---- phase 1: scores (fp16 proj gather, 64B/row) ----
#pragma unroll 8
    for (int it = 0; it < 16; ++it) {
        int k = it * 64 + g;
        int e = sadj[k];
        float4 p4 = proj4[e * 4 + l4];
        const __half2* ph = reinterpret_cast<const __half2*>(&p4);
        float part = 0.f;
#pragma unroll
        for (int q = 0; q < 4; q++) {
            float2 f = __half22float2(ph[q]);
            part = fmaf(f.x, xr[2 * q], fmaf(f.y, xr[2 * q + 1], part));
        }
        part += __shfl_xor_sync(0xffffffffu, part, 1);
        part += __shfl_xor_sync(0xffffffffu, part, 2);
        if (l4 == 0) {
            float s = ss[k] + part;
            s = s > 0.f ? s : 0.01f * s;             // leaky_relu(0.01)
            ss[k] = (e > 0) ? s : -9e15f;            // mask adj>0
        }
    }
    __syncthreads();

    // ---- phase 2: softmax over k ----
    float m = -3.4e38f;
    for (int k = tid; k < NN; k += 256) m = fmaxf(m, ss[k]);
#pragma unroll
    for (int o = 16; o; o >>= 1) m = fmaxf(m, __shfl_xor_sync(0xffffffffu, m, o));
    if ((tid & 31) == 0) red[tid >> 5] = m;
    __syncthreads();
    if (tid == 0) {
        float t = red[0];
        for (int i = 1; i < 8; i++) t = fmaxf(t, red[i]);
        red[0] = t;
    }
    __syncthreads();
    float M = red[0];
    __syncthreads();

    float Z = 0.f;
    for (int k = tid; k < NN; k += 256) {
        float ev = __expf(ss[k] - M);
        ss[k] = ev;
        Z += ev;
    }
#pragma unroll
    for (int o = 16; o; o >>= 1) Z += __shfl_xor_sync(0xffffffffu, Z, o);
    if ((tid & 31) == 0) red[tid >> 5] = Z;
    __syncthreads();
    if (tid == 0) {
        float t = 0.f;
        for (int i = 0; i < 8; i++) t += red[i];
        red[0] = t;
    }
    __syncthreads();
    float inv = 1.f / red[0];
    for (int k = tid; k < NN; k += 256) {
        float w = ss[k] * inv;
        ss[k] = w;
        g_ws[n * NN + k] = w;
    }
    __syncthreads();

    // ---- phase 3: we[n,:] = sum_k ws[k] * emb_fp16[adj[n,k],:] ----
    float acc[8];
#pragma unroll
    for (int j = 0; j < 8; j++) acc[j] = 0.f;
#pragma unroll 8
    for (int it = 0; it < 16; ++it) {
        int k = it * 64 + g;
        float w = ss[k];
        int e = sadj[k];
        float4 em4 = emb4[e * 4 + l4];
        const __half2* eh = reinterpret_cast<const __half2*>(&em4);
#pragma unroll
        for (int q = 0; q < 4; q++) {
            float2 f = __half22float2(eh[q]);
            acc[2 * q]     = fmaf(w, f.x, acc[2 * q]);
            acc[2 * q + 1] = fmaf(w, f.y, acc[2 * q + 1]);
        }
    }
#pragma unroll
    for (int j = 0; j < 8; j++) swe[g * 33 + l4 * 8 + j] = acc[j];
    __syncthreads();
    if (tid < 32) {
        float a = 0.f;
#pragma unroll 8
        for (int gg = 0; gg < 64; gg++) a += swe[gg * 33 + tid];
        g_we[n * 32 + tid] = a;
    }
}

// ============================================================
// partials of ws @ value (k-split KSPLIT=32), kz=0 also adds we @ Wfe
// tile: 64 m x 128 n (full N), 4x8 per thread, KCH=32
// grid (16, 32) = 512 blocks
// ============================================================
#define ASTR 36
__global__ void __launch_bounds__(256) agg_kernel(const float* __restrict__ Wfe) {
    __shared__ __align__(16) float sA[64 * ASTR];   // [m][kk]
    __shared__ __align__(16) float sB[32 * 128];    // [kk][n]
    int tid = threadIdx.x;
    int bm = blockIdx.x * 64;
    int kz = blockIdx.y;
    int tx = tid & 15, ty = tid >> 4;
    int m0 = ty * 4;
    float acc[4][8];
#pragma unroll
    for (int i = 0; i < 4; i++)
#pragma unroll
        for (int j = 0; j < 8; j++) acc[i][j] = 0.f;

    const int KCH = NN / KSPLIT;   // 32
    {
        int kt = kz * KCH;
#pragma unroll
        for (int j = 0; j < 2; j++) {
            int f = tid + j * 256;            // 0..511 float4
            int mm = f >> 3, c4 = f & 7;
            float4 v = reinterpret_cast<const float4*>(g_ws)[(bm + mm) * 256 + (kt >> 2) + c4];
            *reinterpret_cast<float4*>(&sA[mm * ASTR + c4 * 4]) = v;
        }
#pragma unroll
        for (int j = 0; j < 4; j++) {
            int f = tid + j * 256;            // 0..1023 float4
            reinterpret_cast<float4*>(sB)[f] =
                reinterpret_cast<const float4*>(g_value)[kt * 32 + f];
        }
        __syncthreads();
#pragma unroll
        for (int kk = 0; kk < 32; kk++) {
            float a0 = sA[(m0 + 0) * ASTR + kk];
            float a1 = sA[(m0 + 1) * ASTR + kk];
            float a2 = sA[(m0 + 2) * ASTR + kk];
            float a3 = sA[(m0 + 3) * ASTR + kk];
            float4 bL = *reinterpret_cast<const float4*>(&sB[kk * 128 + tx * 4]);
            float4 bH = *reinterpret_cast<const float4*>(&sB[kk * 128 + 64 + tx * 4]);
            float bb[8] = {bL.x, bL.y, bL.z, bL.w, bH.x, bH.y, bH.z, bH.w};
            float aa[4] = {a0, a1, a2, a3};
#pragma unroll
            for (int i = 0; i < 4; i++)
#pragma unroll
                for (int j = 0; j < 8; j++)
                    acc[i][j] = fmaf(aa[i], bb[j], acc[i][j]);
        }
    }

    if (kz == 0) {
        // epilogue: + we[bm:bm+64, 0:32] @ Wfe[0:32, 0:128]
        __syncthreads();
#pragma unroll
        for (int j = 0; j < 2; j++) {
            int f = tid + j * 256;
            int mm = f >> 3, c4 = f & 7;
            float4 v = reinterpret_cast<const float4*>(g_we)[mm * 8 + c4 + bm * 8];
            *reinterpret_cast<float4*>(&sA[mm * ASTR + c4 * 4]) = v;
        }
#pragma unroll
        for (int j = 0; j < 4; j++) {
            int f = tid + j * 256;
            reinterpret_cast<float4*>(sB)[f] =
                reinterpret_cast<const float4*>(Wfe)[f];
        }
        __syncthreads();
#pragma unroll
        for (int kk = 0; kk < 32; kk++) {
            float a0 = sA[(m0 + 0) * ASTR + kk];
            float a1 = sA[(m0 + 1) * ASTR + kk];
            float a2 = sA[(m0 + 2) * ASTR + kk];
            float a3 = sA[(m0 + 3) * ASTR + kk];
            float4 bL = *reinterpret_cast<const float4*>(&sB[kk * 128 + tx * 4]);
            float4 bH = *reinterpret_cast<const float4*>(&sB[kk * 128 + 64 + tx * 4]);
            float bb[8] = {bL.x, bL.y, bL.z, bL.w, bH.x, bH.y, bH.z, bH.w};
            float aa[4] = {a0, a1, a2, a3};
#pragma unroll
            for (int i = 0; i < 4; i++)
#pragma unroll
                for (int j = 0; j < 8; j++)
                    acc[i][j] = fmaf(aa[i], bb[j], acc[i][j]);
        }
    }

#pragma unroll
    for (int i = 0; i < 4; i++) {
        float* dst = &g_part[(kz * NN + bm + m0 + i) * ODIM];
        *reinterpret_cast<float4*>(dst + tx * 4) =
            make_float4(acc[i][0], acc[i][1], acc[i][2], acc[i][3]);
        *reinterpret_cast<float4*>(dst + 64 + tx * 4) =
            make_float4(acc[i][4], acc[i][5], acc[i][6], acc[i][7]);
    }
}

// ============================================================
// out[n, 128:256] = sum_kz part[kz] + bfe
// ============================================================
__global__ void __launch_bounds__(256) reduce_kernel(const float* __restrict__ bfe,
                                                     float* __restrict__ outp) {
    int idx = blockIdx.x * 256 + threadIdx.x;   // 0..131071
    int n = idx >> 7, c = idx & 127;
    float v = bfe[c];
#pragma unroll
    for (int kz = 0; kz < KSPLIT; kz++)
        v += g_part[kz * NN * ODIM + idx];
    outp[n * (2 * ODIM) + ODIM + c] = v;
}

extern "C" void kernel_launch(void* const* d_in, const int* in_sizes, int n_in,
                              void* d_out, int out_size) {
    const float* x     = (const float*)d_in[0];
    const float* neigh = (const float*)d_in[1];
    const float* emb   = (const float*)d_in[2];
    const int*   adj   = (const int*)d_in[3];
    const float* Wx1 = (const float*)d_in[4];  const float* bx1 = (const float*)d_in[5];
    const float* Wx2 = (const float*)d_in[6];  const float* bx2 = (const float*)d_in[7];
    const float* Wn1 = (const float*)d_in[8];  const float* bn1 = (const float*)d_in[9];
    const float* Wn2 = (const float*)d_in[10]; const float* bn2 = (const float*)d_in[11];
    const float* We  = (const float*)d_in[12]; const float* be  = (const float*)d_in[13];
    const float* Wv  = (const float*)d_in[14]; const float* bv  = (const float*)d_in[15];
    const float* Wfe = (const float*)d_in[16]; const float* bfe = (const float*)d_in[17];
    const float* Wfx = (const float*)d_in[18]; const float* bfx = (const float*)d_in[19];
    float* out = (float*)d_out;

    pre_kernel<<<NB_PROJ + NB_CVT + 2 * NB_ATT + 2 * NB_GEMM, 256>>>(
        emb, We, be,
        x, Wx1, bx1, Wx2, bx2,
        neigh, Wn1, bn1, Wn2, bn2,
        Wv, bv, Wfx, bfx, out);
    s1_kernel<<<dim3(16, 32), 256>>>();
    row_kernel<<<NN, 256>>>(adj);
    agg_kernel<<<dim3(16, KSPLIT), 256>>>(Wfe);
    reduce_kernel<<<512, 256>>>(bfe, out);
}

// round 10
// speedup vs baseline: 2.4150x; 1.0231x over previous
#include <cuda_runtime.h>
#include <cuda_fp16.h>
#include <math.h>

#define NN   1024
#define IND  256
#define ED   32
#define HID  32
#define ODIM 128
#define NE   100000

#define NB_PROJ (NE / 32)        // 3125
#define NB_CVT  1563             // emb fp32 -> fp16 (2048 elems/block)
#define KSPLIT  32               // agg k-split

// ---- scratch (device globals; no allocation allowed) ----
__device__ __half g_projh[NE * ED];      // fp16 tanh(edge_emb @ We + be)
__device__ __half g_embh[NE * ED];       // fp16 copy of edge_emb
__device__ float g_xatt[NN * HID];
__device__ float g_natt[NN * HID];
__device__ float g_value[NN * ODIM];     // neigh @ Wv + bv
__device__ float g_s1[NN * NN];          // x_att @ n_att^T
__device__ float g_ws[NN * NN];          // softmax weights
__device__ float g_we[NN * ED];          // ws-weighted edge embeddings
__device__ float g_part[KSPLIT * NN * ODIM];  // ksplit partials of ws@value

// single-instruction MUFU tanh (sm_75+), ~2^-11 max error
__device__ __forceinline__ float fast_tanh(float x) {
    float y;
    asm("tanh.approx.f32 %0, %1;" : "=f"(y) : "f"(x));
    return y;
}

// ============================================================
// projcvt: proj[e,:] = tanh(emb[e,:] @ We + be) -> fp16
//          plus fp16 copy of emb
// ============================================================
__global__ void __launch_bounds__(256) projcvt_kernel(const float* __restrict__ emb,
                                                      const float* __restrict__ We,
                                                      const float* __restrict__ be) {
    int bid = blockIdx.x;
    if (bid < NB_PROJ) {
        __shared__ float sW[1024];
        __shared__ float sb[32];
        __shared__ __align__(16) float sx[1024];
        int tid = threadIdx.x;
        for (int i = tid; i < 1024; i += 256) sW[i] = We[i];
        if (tid < 32) sb[tid] = be[tid];
        int rows0 = bid * 32;
        reinterpret_cast<float4*>(sx)[tid] =
            reinterpret_cast<const float4*>(emb)[rows0 * 8 + tid];
        __syncthreads();
        int col = tid & 31;
        int r0 = (tid >> 5) * 4;
        float acc0 = sb[col], acc1 = acc0, acc2 = acc0, acc3 = acc0;
#pragma unroll
        for (int d = 0; d < 32; d++) {
            float w = sW[d * 32 + col];
            acc0 = fmaf(sx[(r0 + 0) * 32 + d], w, acc0);
            acc1 = fmaf(sx[(r0 + 1) * 32 + d], w, acc1);
            acc2 = fmaf(sx[(r0 + 2) * 32 + d], w, acc2);
            acc3 = fmaf(sx[(r0 + 3) * 32 + d], w, acc3);
        }
        g_projh[(rows0 + r0 + 0) * 32 + col] = __float2half(fast_tanh(acc0));
        g_projh[(rows0 + r0 + 1) * 32 + col] = __float2half(fast_tanh(acc1));
        g_projh[(rows0 + r0 + 2) * 32 + col] = __float2half(fast_tanh(acc2));
        g_projh[(rows0 + r0 + 3) * 32 + col] = __float2half(fast_tanh(acc3));
    } else {
        int blk = bid - NB_PROJ;
        int base = blk * 2048 + threadIdx.x * 8;
        if (base >= NE * ED) return;
        float4 a = *reinterpret_cast<const float4*>(emb + base);
        float4 b = *reinterpret_cast<const float4*>(emb + base + 4);
        __half2 h[4];
        h[0] = __floats2half2_rn(a.x, a.y);
        h[1] = __floats2half2_rn(a.z, a.w);
        h[2] = __floats2half2_rn(b.x, b.y);
        h[3] = __floats2half2_rn(b.z, b.w);
        *reinterpret_cast<float4*>(&g_embh[base]) = *reinterpret_cast<float4*>(h);
    }
}

// ============================================================
// attention MLPs for x and neigh (256 blocks; bid<128 -> x)
// ============================================================
__global__ void __launch_bounds__(256) att2_kernel(
    const float* __restrict__ x, const float* __restrict__ Wx1,
    const float* __restrict__ bx1, const float* __restrict__ Wx2,
    const float* __restrict__ bx2,
    const float* __restrict__ neigh, const float* __restrict__ Wn1,
    const float* __restrict__ bn1, const float* __restrict__ Wn2,
    const float* __restrict__ bn2) {
    __shared__ float sx[8][IND];
    int which = blockIdx.x >> 7;            // 0: x, 1: neigh
    int blk = blockIdx.x & 127;
    const float* X  = which ? neigh : x;
    const float* W1 = which ? Wn1 : Wx1;
    const float* b1 = which ? bn1 : bx1;
    const float* W2 = which ? Wn2 : Wx2;
    const float* b2 = which ? bn2 : bx2;
    float* dst = which ? g_natt : g_xatt;

    int warp = threadIdx.x >> 5, lane = threadIdx.x & 31;
    int row = blk * 8 + warp;
    for (int d = lane; d < IND; d += 32) sx[warp][d] = X[row * IND + d];
    __syncwarp();
    float acc = b1[lane];
#pragma unroll 8
    for (int d = 0; d < IND; d++)
        acc = fmaf(sx[warp][d], W1[d * 32 + lane], acc);
    float h = fast_tanh(acc);
    float a2 = b2[lane];
#pragma unroll
    for (int j = 0; j < 32; j++)
        a2 = fmaf(__shfl_sync(0xffffffffu, h, j), W2[j * 32 + lane], a2);
    dst[row * 32 + lane] = a2;
}

// ============================================================
// fused pair of 256->128 GEMMs (128 blocks; z = bid>>6)
// ============================================================
__global__ void __launch_bounds__(256) gemm2_kernel(
    const float* __restrict__ neigh, const float* __restrict__ Wv,
    const float* __restrict__ bv,
    const float* __restrict__ x, const float* __restrict__ Wfx,
    const float* __restrict__ bfx, float* __restrict__ outp) {
    __shared__ __align__(16) float sX[16 * IND];
    __shared__ __align__(16) float sW[32 * 128];
    int z = blockIdx.x >> 6;
    int blk = blockIdx.x & 63;
    const float* X = z ? x : neigh;
    const float* W = z ? Wfx : Wv;
    const float* b = z ? bfx : bv;
    int tid = threadIdx.x;
    int r0 = blk * 16;
#pragma unroll
    for (int j = 0; j < 4; j++) {
        int f = tid + j * 256;
        int r = f >> 6, c4 = f & 63;
        reinterpret_cast<float4*>(sX)[f] =
            reinterpret_cast<const float4*>(X)[(r0 + r) * 64 + c4];
    }
    int c = tid & 127;
    int rh = tid >> 7;
    float acc[8];
    float bb = b[c];
#pragma unroll
    for (int i = 0; i < 8; i++) acc[i] = bb;

    for (int kt = 0; kt < IND; kt += 32) {
        __syncthreads();
#pragma unroll
        for (int j = 0; j < 4; j++) {
            int f = tid + j * 256;
            int rr = f >> 5, cc = f & 31;
            reinterpret_cast<float4*>(sW)[f] =
                reinterpret_cast<const float4*>(W)[(kt + rr) * 32 + cc];
        }
        __syncthreads();
#pragma unroll
        for (int d = 0; d < 32; d++) {
            float w = sW[d * 128 + c];
#pragma unroll
            for (int i = 0; i < 8; i++)
                acc[i] = fmaf(sX[(rh * 8 + i) * IND + kt + d], w, acc[i]);
        }
    }
    if (z == 0) {
#pragma unroll
        for (int i = 0; i < 8; i++) g_value[(r0 + rh * 8 + i) * ODIM + c] = acc[i];
    } else {
#pragma unroll
        for (int i = 0; i < 8; i++) outp[(r0 + rh * 8 + i) * (2 * ODIM) + c] = acc[i];
    }
}

// ============================================================
// S1 = x_att @ n_att^T   (64x32 tiles, grid (16,32))
// ============================================================
__global__ void __launch_bounds__(256) s1_kernel() {
    __shared__ __align__(16) float sA[32 * 64];
    __shared__ __align__(16) float sB[32 * 32];
    int tid = threadIdx.x;
    int bm = blockIdx.x * 64, bk = blockIdx.y * 32;
#pragma unroll
    for (int j = 0; j < 2; j++) {
        int f = tid + j * 256;
        int m = f >> 3, d4 = f & 7;
        float4 va = reinterpret_cast<const float4*>(g_xatt)[(bm + m) * 8 + d4];
        sA[(d4 * 4 + 0) * 64 + m] = va.x;
        sA[(d4 * 4 + 1) * 64 + m] = va.y;
        sA[(d4 * 4 + 2) * 64 + m] = va.z;
        sA[(d4 * 4 + 3) * 64 + m] = va.w;
    }
    {
        int m = tid >> 3, d4 = tid & 7;
        float4 vb = reinterpret_cast<const float4*>(g_natt)[(bk + m) * 8 + d4];
        sB[(d4 * 4 + 0) * 32 + m] = vb.x;
        sB[(d4 * 4 + 1) * 32 + m] = vb.y;
        sB[(d4 * 4 + 2) * 32 + m] = vb.z;
        sB[(d4 * 4 + 3) * 32 + m] = vb.w;
    }
    __syncthreads();
    int tx = tid & 15, ty = tid >> 4;
    float acc[4][2];
#pragma unroll
    for (int i = 0; i < 4; i++) { acc[i][0] = 0.f; acc[i][1] = 0.f; }
#pragma unroll
    for (int d = 0; d < 32; d++) {
        float4 a4 = *reinterpret_cast<const float4*>(&sA[d * 64 + ty * 4]);
        float b0 = sB[d * 32 + tx * 2];
        float b1 = sB[d * 32 + tx * 2 + 1];
        float a[4] = {a4.x, a4.y, a4.z, a4.w};
#pragma unroll
        for (int i = 0; i < 4; i++) {
            acc[i][0] = fmaf(a[i], b0, acc[i][0]);
            acc[i][1] = fmaf(a[i], b1, acc[i][1]);
        }
    }
#pragma unroll
    for (int i = 0; i < 4; i++) {
        g_s1[(bm + ty * 4 + i) * NN + bk + tx * 2]     = acc[i][0];
        g_s1[(bm + ty * 4 + i) * NN + bk + tx * 2 + 1] = acc[i][1];
    }
}

// ============================================================
// per-row: scores -> softmax -> ws, weighted emb sum
// ============================================================
__global__ void __launch_bounds__(256) row_kernel(const int* __restrict__ adj) {
    __shared__ int sadj[NN];
    __shared__ float ss[NN];
    __shared__ __align__(16) float sx[32];
    __shared__ float red[8];
    __shared__ __align__(16) float swe[64 * 33];

    int n = blockIdx.x;
    int tid = threadIdx.x;
    for (int k = tid; k < NN; k += 256) {
        sadj[k] = adj[n * NN + k];
        ss[k] = g_s1[n * NN + k];
    }
    if (tid < 32) sx[tid] = g_xatt[n * 32 + tid];
    __syncthreads();

    int g = tid >> 2, l4 = tid & 3;
    float xr[8];
#pragma unroll
    for (int j = 0; j < 8; j++) xr[j] = sx[l4 * 8 + j];

    const float4* proj4 = reinterpret_cast<const float4*>(g_projh);
    const float4* emb4  = reinterpret_cast<const float4*>(g_embh);

#pragma unroll 8
    for (int it = 0; it < 16; ++it) {
        int k = it * 64 + g;
        int e = sadj[k];
        float4 p4 = proj4[e * 4 + l4];
        const __half2* ph = reinterpret_cast<const __half2*>(&p4);
        float part = 0.f;
#pragma unroll
        for (int q = 0; q < 4; q++) {
            float2 f = __half22float2(ph[q]);
            part = fmaf(f.x, xr[2 * q], fmaf(f.y, xr[2 * q + 1], part));
        }
        part += __shfl_xor_sync(0xffffffffu, part, 1);
        part += __shfl_xor_sync(0xffffffffu, part, 2);
        if (l4 == 0) {
            float s = ss[k] + part;
            s = s > 0.f ? s : 0.01f * s;
            ss[k] = (e > 0) ? s : -9e15f;
        }
    }
    __syncthreads();

    float m = -3.4e38f;
    for (int k = tid; k < NN; k += 256) m = fmaxf(m, ss[k]);
#pragma unroll
    for (int o = 16; o; o >>= 1) m = fmaxf(m, __shfl_xor_sync(0xffffffffu, m, o));
    if ((tid & 31) == 0) red[tid >> 5] = m;
    __syncthreads();
    if (tid == 0) {
        float t = red[0];
        for (int i = 1; i < 8; i++) t = fmaxf(t, red[i]);
        red[0] = t;
    }
    __syncthreads();
    float M = red[0];
    __syncthreads();

    float Z = 0.f;
    for (int k = tid; k < NN; k += 256) {
        float ev = __expf(ss[k] - M);
        ss[k] = ev;
        Z += ev;
    }
#pragma unroll
    for (int o = 16; o; o >>= 1) Z += __shfl_xor_sync(0xffffffffu, Z, o);
    if ((tid & 31) == 0) red[tid >> 5] = Z;
    __syncthreads();
    if (tid == 0) {
        float t = 0.f;
        for (int i = 0; i < 8; i++) t += red[i];
        red[0] = t;
    }
    __syncthreads();
    float inv = 1.f / red[0];
    for (int k = tid; k < NN; k += 256) {
        float w = ss[k] * inv;
        ss[k] = w;
        g_ws[n * NN + k] = w;
    }
    __syncthreads();

    float acc[8];
#pragma unroll
    for (int j = 0; j < 8; j++) acc[j] = 0.f;
#pragma unroll 8
    for (int it = 0; it < 16; ++it) {
        int k = it * 64 + g;
        float w = ss[k];
        int e = sadj[k];
        float4 em4 = emb4[e * 4 + l4];
        const __half2* eh = reinterpret_cast<const __half2*>(&em4);
#pragma unroll
        for (int q = 0; q < 4; q++) {
            float2 f = __half22float2(eh[q]);
            acc[2 * q]     = fmaf(w, f.x, acc[2 * q]);
            acc[2 * q + 1] = fmaf(w, f.y, acc[2 * q + 1]);
        }
    }
#pragma unroll
    for (int j = 0; j < 8; j++) swe[g * 33 + l4 * 8 + j] = acc[j];
    __syncthreads();
    if (tid < 32) {
        float a = 0.f;
#pragma unroll 8
        for (int gg = 0; gg < 64; gg++) a += swe[gg * 33 + tid];
        g_we[n * 32 + tid] = a;
    }
}

// ============================================================
// partials of ws @ value (KSPLIT=32), kz=0 adds we @ Wfe
// ============================================================
#define ASTR 36
__global__ void __launch_bounds__(256) agg_kernel(const float* __restrict__ Wfe) {
    __shared__ __align__(16) float sA[64 * ASTR];
    __shared__ __align__(16) float sB[32 * 128];
    int tid = threadIdx.x;
    int bm = blockIdx.x * 64;
    int kz = blockIdx.y;
    int tx = tid & 15, ty = tid >> 4;
    int m0 = ty * 4;
    float acc[4][8];
#pragma unroll
    for (int i = 0; i < 4; i++)
#pragma unroll
        for (int j = 0; j < 8; j++) acc[i][j] = 0.f;

    const int KCH = NN / KSPLIT;   // 32
    {
        int kt = kz * KCH;
#pragma unroll
        for (int j = 0; j < 2; j++) {
            int f = tid + j * 256;
            int mm = f >> 3, c4 = f & 7;
            float4 v = reinterpret_cast<const float4*>(g_ws)[(bm + mm) * 256 + (kt >> 2) + c4];
            *reinterpret_cast<float4*>(&sA[mm * ASTR + c4 * 4]) = v;
        }
#pragma unroll
        for (int j = 0; j < 4; j++) {
            int f = tid + j * 256;
            reinterpret_cast<float4*>(sB)[f] =
                reinterpret_cast<const float4*>(g_value)[kt * 32 + f];
        }
        __syncthreads();
#pragma unroll
        for (int kk = 0; kk < 32; kk++) {
            float a0 = sA[(m0 + 0) * ASTR + kk];
            float a1 = sA[(m0 + 1) * ASTR + kk];
            float a2 = sA[(m0 + 2) * ASTR + kk];
            float a3 = sA[(m0 + 3) * ASTR + kk];
            float4 bL = *reinterpret_cast<const float4*>(&sB[kk * 128 + tx * 4]);
            float4 bH = *reinterpret_cast<const float4*>(&sB[kk * 128 + 64 + tx * 4]);
            float bb[8] = {bL.x, bL.y, bL.z, bL.w, bH.x, bH.y, bH.z, bH.w};
            float aa[4] = {a0, a1, a2, a3};
#pragma unroll
            for (int i = 0; i < 4; i++)
#pragma unroll
                for (int j = 0; j < 8; j++)
                    acc[i][j] = fmaf(aa[i], bb[j], acc[i][j]);
        }
    }

    if (kz == 0) {
        __syncthreads();
#pragma unroll
        for (int j = 0; j < 2; j++) {
            int f = tid + j * 256;
            int mm = f >> 3, c4 = f & 7;
            float4 v = reinterpret_cast<const float4*>(g_we)[mm * 8 + c4 + bm * 8];
            *reinterpret_cast<float4*>(&sA[mm * ASTR + c4 * 4]) = v;
        }
#pragma unroll
        for (int j = 0; j < 4; j++) {
            int f = tid + j * 256;
            reinterpret_cast<float4*>(sB)[f] =
                reinterpret_cast<const float4*>(Wfe)[f];
        }
        __syncthreads();
#pragma unroll
        for (int kk = 0; kk < 32; kk++) {
            float a0 = sA[(m0 + 0) * ASTR + kk];
            float a1 = sA[(m0 + 1) * ASTR + kk];
            float a2 = sA[(m0 + 2) * ASTR + kk];
            float a3 = sA[(m0 + 3) * ASTR + kk];
            float4 bL = *reinterpret_cast<const float4*>(&sB[kk * 128 + tx * 4]);
            float4 bH = *reinterpret_cast<const float4*>(&sB[kk * 128 + 64 + tx * 4]);
            float bb[8] = {bL.x, bL.y, bL.z, bL.w, bH.x, bH.y, bH.z, bH.w};
            float aa[4] = {a0, a1, a2, a3};
#pragma unroll
            for (int i = 0; i < 4; i++)
#pragma unroll
                for (int j = 0; j < 8; j++)
                    acc[i][j] = fmaf(aa[i], bb[j], acc[i][j]);
        }
    }

#pragma unroll
    for (int i = 0; i < 4; i++) {
        float* dst = &g_part[(kz * NN + bm + m0 + i) * ODIM];
        *reinterpret_cast<float4*>(dst + tx * 4) =
            make_float4(acc[i][0], acc[i][1], acc[i][2], acc[i][3]);
        *reinterpret_cast<float4*>(dst + 64 + tx * 4) =
            make_float4(acc[i][4], acc[i][5], acc[i][6], acc[i][7]);
    }
}

// ============================================================
// out[n, 128:256] = sum_kz part[kz] + bfe   (float4, 128 blocks)
// ============================================================
__global__ void __launch_bounds__(256) reduce_kernel(const float* __restrict__ bfe,
                                                     float* __restrict__ outp) {
    int idx4 = blockIdx.x * 256 + threadIdx.x;   // 0..32767 float4
    int n = idx4 >> 5, c4 = idx4 & 31;
    const float4* p4 = reinterpret_cast<const float4*>(g_part);
    float4 v = reinterpret_cast<const float4*>(bfe)[c4];
#pragma unroll
    for (int kz = 0; kz < KSPLIT; kz++) {
        float4 t = p4[kz * (NN * ODIM / 4) + idx4];
        v.x += t.x; v.y += t.y; v.z += t.z; v.w += t.w;
    }
    reinterpret_cast<float4*>(outp)[n * 64 + 32 + c4] = v;
}

extern "C" void kernel_launch(void* const* d_in, const int* in_sizes, int n_in,
                              void* d_out, int out_size) {
    const float* x     = (const float*)d_in[0];
    const float* neigh = (const float*)d_in[1];
    const float* emb   = (const float*)d_in[2];
    const int*   adj   = (const int*)d_in[3];
    const float* Wx1 = (const float*)d_in[4];  const float* bx1 = (const float*)d_in[5];
    const float* Wx2 = (const float*)d_in[6];  const float* bx2 = (const float*)d_in[7];
    const float* Wn1 = (const float*)d_in[8];  const float* bn1 = (const float*)d_in[9];
    const float* Wn2 = (const float*)d_in[10]; const float* bn2 = (const float*)d_in[11];
    const float* We  = (const float*)d_in[12]; const float* be  = (const float*)d_in[13];
    const float* Wv  = (const float*)d_in[14]; const float* bv  = (const float*)d_in[15];
    const float* Wfe = (const float*)d_in[16]; const float* bfe = (const float*)d_in[17];
    const float* Wfx = (const float*)d_in[18]; const float* bfx = (const float*)d_in[19];
    float* out = (float*)d_out;

    // fork two side streams off the capture (default) stream
    cudaStream_t sB, sC;
    cudaStreamCreateWithFlags(&sB, cudaStreamNonBlocking);
    cudaStreamCreateWithFlags(&sC, cudaStreamNonBlocking);
    cudaEvent_t evRoot, evB, evC;
    cudaEventCreateWithFlags(&evRoot, cudaEventDisableTiming);
    cudaEventCreateWithFlags(&evB, cudaEventDisableTiming);
    cudaEventCreateWithFlags(&evC, cudaEventDisableTiming);

    cudaEventRecord(evRoot, 0);
    cudaStreamWaitEvent(sB, evRoot, 0);
    cudaStreamWaitEvent(sC, evRoot, 0);

    // stream B: edge-table work (needed by row)
    projcvt_kernel<<<NB_PROJ + NB_CVT, 256, 0, sB>>>(emb, We, be);
    cudaEventRecord(evB, sB);

    // stream C: value + out[:, :128] (needed by agg)
    gemm2_kernel<<<128, 256, 0, sC>>>(neigh, Wv, bv, x, Wfx, bfx, out);
    cudaEventRecord(evC, sC);

    // default stream: att -> s1, then join B -> row, join C -> agg -> reduce
    att2_kernel<<<256, 256>>>(x, Wx1, bx1, Wx2, bx2, neigh, Wn1, bn1, Wn2, bn2);
    s1_kernel<<<dim3(16, 32), 256>>>();
    cudaStreamWaitEvent(0, evB, 0);
    row_kernel<<<NN, 256>>>(adj);
    cudaStreamWaitEvent(0, evC, 0);
    agg_kernel<<<dim3(16, KSPLIT), 256>>>(Wfe);
    reduce_kernel<<<128, 256>>>(bfe, out);

    cudaEventDestroy(evRoot);
    cudaEventDestroy(evB);
    cudaEventDestroy(evC);
    cudaStreamDestroy(sB);
    cudaStreamDestroy(sC);
}